// round 7
// baseline (speedup 1.0000x reference)
#include <cuda_runtime.h>
#include <cstdint>
#include <cstddef>

// Problem constants (fixed by the reference setup)
#define BB   2
#define MMT  64     // m (outer-mean dim)
#define NNT  256    // i / j
#define DDT  256    // d
#define HHT  256    // h
#define ROWS (BB*MMT*NNT)   // 32768 token rows (b,m,i)

typedef unsigned long long u64;

// ---------------- packed f32x2 helpers (Blackwell, base-arch feature) --------
#define FMA2(d, a, b, c) \
    asm("fma.rn.f32x2 %0, %1, %2, %3;" : "=l"(d) : "l"(a), "l"(b), "l"(c))
#define PACK2(out, lo, hi) \
    asm("mov.b64 %0, {%1, %2};" : "=l"(out) : "f"(lo), "f"(hi))
#define UNPACK2(lo, hi, in) \
    asm("mov.b64 {%0, %1}, %2;" : "=f"(lo), "=f"(hi) : "l"(in))

// ---------------- scratch (device globals; no allocations allowed) ----------
__device__ float g_xn[ROWS * DDT];                       //  33.5 MB  layernormed x
__device__ float g_L [ROWS * HHT];                       //  33.5 MB  left  proj (masked)
__device__ float g_R [ROWS * HHT];                       //  33.5 MB  right proj (masked)
__device__ float g_outer[(size_t)BB * NNT * NNT * HHT];  // 134   MB  outer[b][i][j][h]
__device__ float g_maskf[ROWS];                          // float mask (b,m,i)
__device__ float g_cinv[BB * NNT * NNT];                 // 1/(64*(cnt+eps))
__device__ int   g_mask_mode;                            // 0=int32, 1=float32, 2=uint8

// ---------------- kernel 0a: detect mask dtype ------------------------------
__global__ void detect_mask_kernel(const unsigned int* p) {
    __shared__ int s_nonbin, s_nonfp;
    if (threadIdx.x == 0) { s_nonbin = 0; s_nonfp = 0; }
    __syncthreads();
    int nonbin = 0, nonfp = 0;
    for (int idx = threadIdx.x; idx < 8192; idx += 256) {
        unsigned int v = p[idx];
        if (v != 0u && v != 1u)           nonbin = 1;
        if (v != 0u && v != 0x3F800000u)  nonfp  = 1;
    }
    if (nonbin) atomicOr(&s_nonbin, 1);
    if (nonfp)  atomicOr(&s_nonfp, 1);
    __syncthreads();
    if (threadIdx.x == 0) {
        int mode;
        if      (!s_nonbin) mode = 0;   // int32 0/1
        else if (!s_nonfp)  mode = 1;   // float32 0.0/1.0
        else                mode = 2;   // uint8 / bool bytes
        g_mask_mode = mode;
    }
}

// ---------------- kernel 0b: expand mask to float ----------------------------
__global__ void expand_mask_kernel(const void* p) {
    int r = blockIdx.x * 256 + threadIdx.x;  // 0..32767
    int mode = g_mask_mode;
    float f;
    if (mode == 0)      f = (((const int*)p)[r]           != 0)    ? 1.0f : 0.0f;
    else if (mode == 1) f = (((const float*)p)[r]         != 0.0f) ? 1.0f : 0.0f;
    else                f = (((const unsigned char*)p)[r] != 0)    ? 1.0f : 0.0f;
    g_maskf[r] = f;
}

// ---------------- kernel 1: LayerNorm over d=256 (one block per row) --------
__global__ void __launch_bounds__(256) ln_kernel(const float* __restrict__ x,
                                                 const float* __restrict__ w,
                                                 const float* __restrict__ bvec) {
    __shared__ float red[256];
    __shared__ float s_mu, s_rstd;
    int row = blockIdx.x;
    int t = threadIdx.x;
    float v = x[(size_t)row * DDT + t];
    red[t] = v;
    __syncthreads();
    for (int s = 128; s > 0; s >>= 1) {
        if (t < s) red[t] += red[t + s];
        __syncthreads();
    }
    if (t == 0) s_mu = red[0] * (1.0f / DDT);
    __syncthreads();
    float mu = s_mu;
    float dv = v - mu;
    red[t] = dv * dv;
    __syncthreads();
    for (int s = 128; s > 0; s >>= 1) {
        if (t < s) red[t] += red[t + s];
        __syncthreads();
    }
    if (t == 0) s_rstd = rsqrtf(red[0] * (1.0f / DDT) + 1e-5f);
    __syncthreads();
    g_xn[(size_t)row * DDT + t] = dv * s_rstd * w[t] + bvec[t];
}

// ---------------- kernel 2: projections (SGEMM 32768x256 @ 256x256, x2) -----
// C tile 128x128, BK=16, 256 threads, 8x8 microtile, packed f32x2 FMA.
__global__ void __launch_bounds__(256) proj_kernel(const float* __restrict__ Wl,
                                                   const float* __restrict__ bl,
                                                   const float* __restrict__ Wr,
                                                   const float* __restrict__ br) {
    __shared__ __align__(16) float As[16][132];   // [k][row], padded
    __shared__ __align__(16) float Bs[16][128];   // [k][n]

    const float* W    = blockIdx.z ? Wr : Wl;
    const float* bias = blockIdx.z ? br : bl;
    float*       Out  = blockIdx.z ? g_R : g_L;

    int tid = threadIdx.x;
    int tx = tid & 15, ty = tid >> 4;
    int r0 = blockIdx.y * 128;   // row tile
    int n0 = blockIdx.x * 128;   // h tile

    u64 acc2[8][4];              // acc2[i][jp] = (C[i][2jp], C[i][2jp+1])
#pragma unroll
    for (int i = 0; i < 8; i++)
#pragma unroll
        for (int j = 0; j < 4; j++) acc2[i][j] = 0ULL;

    for (int kb = 0; kb < DDT; kb += 16) {
        // A tile: 128 rows x 16 k, transposed into As[k][row]
#pragma unroll
        for (int it = 0; it < 2; it++) {
            int f = it * 256 + tid;
            int row = f >> 2, kv = f & 3;
            float4 v = *(const float4*)&g_xn[(size_t)(r0 + row) * DDT + kb + kv * 4];
            As[kv * 4 + 0][row] = v.x;
            As[kv * 4 + 1][row] = v.y;
            As[kv * 4 + 2][row] = v.z;
            As[kv * 4 + 3][row] = v.w;
        }
        // B tile: 16 k x 128 n
#pragma unroll
        for (int it = 0; it < 2; it++) {
            int f = it * 256 + tid;
            int k = f >> 5, nv = f & 31;
            *(float4*)&Bs[k][nv * 4] =
                *(const float4*)&W[(size_t)(kb + k) * HHT + n0 + nv * 4];
        }
        __syncthreads();
#pragma unroll
        for (int k = 0; k < 16; k++) {
            float4 a0 = *(const float4*)&As[k][ty * 8];
            float4 a1 = *(const float4*)&As[k][ty * 8 + 4];
            const u64* bp = (const u64*)&Bs[k][tx * 8];
            u64 b0 = bp[0], b1 = bp[1], b2 = bp[2], b3 = bp[3];
            float av[8] = {a0.x, a0.y, a0.z, a0.w, a1.x, a1.y, a1.z, a1.w};
            u64 aa[8];
#pragma unroll
            for (int i = 0; i < 8; i++) PACK2(aa[i], av[i], av[i]);
#pragma unroll
            for (int i = 0; i < 8; i++) {
                FMA2(acc2[i][0], aa[i], b0, acc2[i][0]);
                FMA2(acc2[i][1], aa[i], b1, acc2[i][1]);
                FMA2(acc2[i][2], aa[i], b2, acc2[i][2]);
                FMA2(acc2[i][3], aa[i], b3, acc2[i][3]);
            }
        }
        __syncthreads();
    }

    float bb[8];
#pragma unroll
    for (int j = 0; j < 8; j++) bb[j] = bias[n0 + tx * 8 + j];

#pragma unroll
    for (int i = 0; i < 8; i++) {
        int row = r0 + ty * 8 + i;
        float mf = g_maskf[row];
#pragma unroll
        for (int jv = 0; jv < 2; jv++) {
            float c0, c1, c2, c3;
            UNPACK2(c0, c1, acc2[i][jv * 2 + 0]);
            UNPACK2(c2, c3, acc2[i][jv * 2 + 1]);
            float4 v;
            v.x = (c0 + bb[jv * 4 + 0]) * mf;
            v.y = (c1 + bb[jv * 4 + 1]) * mf;
            v.z = (c2 + bb[jv * 4 + 2]) * mf;
            v.w = (c3 + bb[jv * 4 + 3]) * mf;
            *(float4*)&Out[(size_t)row * HHT + n0 + tx * 8 + jv * 4] = v;
        }
    }
}

// ---------------- kernel 3: pair-count inverse -------------------------------
__global__ void __launch_bounds__(256) cnt_kernel() {
    int b = blockIdx.x >> 8;
    int i = blockIdx.x & 255;
    int j = threadIdx.x;
    __shared__ float mi[MMT];
    if (j < MMT) mi[j] = g_maskf[(b * MMT + j) * NNT + i];
    __syncthreads();
    float s = 0.0f;
#pragma unroll 8
    for (int m = 0; m < MMT; m++)
        s = fmaf(mi[m], g_maskf[(b * MMT + m) * NNT + j], s);
    g_cinv[((size_t)b * NNT + i) * NNT + j] = 1.0f / ((float)MMT * (s + 1e-5f));
}

// ---------------- kernel 4: masked outer-mean contraction over m -------------
// outer[b][i][j][h] = cinv[b][i][j] * sum_m L[b,m,i,h] * R[b,m,j,h]
// Block tile: 64(i) x 32(j) x 8(h); thread micro 8(i) x 4(j) x 2(h).
// The h-pair maps onto packed f32x2 lanes: acc2[ii][jj] = (h_even, h_odd).
__global__ void __launch_bounds__(256) outer_kernel() {
    __shared__ __align__(16) float Ls[8][8][68];  // [m][h][i] (+4 pad)
    __shared__ __align__(16) float Rs[8][8][32];  // [m][h][j]

    int tid = threadIdx.x;
    int hb = blockIdx.x;             // h0 = hb*8
    int jb = blockIdx.y;             // j0 = jb*32
    int zb = blockIdx.z;             // b = zb>>2, i0 = (zb&3)*64
    int b  = zb >> 2;
    int i0 = (zb & 3) * 64;
    int j0 = jb * 32;
    int h0 = hb * 8;

    int jg = tid & 7;
    int hg = (tid >> 3) & 3;
    int ig = tid >> 5;

    u64 acc2[8][4];
#pragma unroll
    for (int ii = 0; ii < 8; ii++)
#pragma unroll
        for (int jj = 0; jj < 4; jj++) acc2[ii][jj] = 0ULL;

    for (int mc = 0; mc < MMT; mc += 8) {
        // Ls: 8m x 64i x 8h  (transpose h<->i while staging)
#pragma unroll
        for (int it = 0; it < 4; it++) {
            int f = it * 256 + tid;
            int hv = f & 1;
            int li = (f >> 1) & 63;
            int lm = f >> 7;
            float4 v = *(const float4*)
                &g_L[(((size_t)(b * MMT + mc + lm) * NNT + i0 + li) * HHT) + h0 + hv * 4];
            Ls[lm][hv * 4 + 0][li] = v.x;
            Ls[lm][hv * 4 + 1][li] = v.y;
            Ls[lm][hv * 4 + 2][li] = v.z;
            Ls[lm][hv * 4 + 3][li] = v.w;
        }
        // Rs: 8m x 32j x 8h
#pragma unroll
        for (int it = 0; it < 2; it++) {
            int f = it * 256 + tid;
            int hv = f & 1;
            int lj = (f >> 1) & 31;
            int lm = f >> 6;
            float4 v = *(const float4*)
                &g_R[(((size_t)(b * MMT + mc + lm) * NNT + j0 + lj) * HHT) + h0 + hv * 4];
            Rs[lm][hv * 4 + 0][lj] = v.x;
            Rs[lm][hv * 4 + 1][lj] = v.y;
            Rs[lm][hv * 4 + 2][lj] = v.z;
            Rs[lm][hv * 4 + 3][lj] = v.w;
        }
        __syncthreads();
#pragma unroll
        for (int lm = 0; lm < 8; lm++) {
            float4 l00 = *(const float4*)&Ls[lm][hg * 2 + 0][ig * 8];
            float4 l01 = *(const float4*)&Ls[lm][hg * 2 + 0][ig * 8 + 4];
            float4 l10 = *(const float4*)&Ls[lm][hg * 2 + 1][ig * 8];
            float4 l11 = *(const float4*)&Ls[lm][hg * 2 + 1][ig * 8 + 4];
            float4 r0v = *(const float4*)&Rs[lm][hg * 2 + 0][jg * 4];
            float4 r1v = *(const float4*)&Rs[lm][hg * 2 + 1][jg * 4];
            float lv0[8] = {l00.x, l00.y, l00.z, l00.w, l01.x, l01.y, l01.z, l01.w};
            float lv1[8] = {l10.x, l10.y, l10.z, l10.w, l11.x, l11.y, l11.z, l11.w};
            float rv0[4] = {r0v.x, r0v.y, r0v.z, r0v.w};
            float rv1[4] = {r1v.x, r1v.y, r1v.z, r1v.w};
            u64 la[8], rb[4];
#pragma unroll
            for (int ii = 0; ii < 8; ii++) PACK2(la[ii], lv0[ii], lv1[ii]);
#pragma unroll
            for (int jj = 0; jj < 4; jj++) PACK2(rb[jj], rv0[jj], rv1[jj]);
#pragma unroll
            for (int ii = 0; ii < 8; ii++)
#pragma unroll
                for (int jj = 0; jj < 4; jj++)
                    FMA2(acc2[ii][jj], la[ii], rb[jj], acc2[ii][jj]);
        }
        __syncthreads();
    }

#pragma unroll
    for (int ii = 0; ii < 8; ii++) {
        int gi = i0 + ig * 8 + ii;
#pragma unroll
        for (int jj = 0; jj < 4; jj++) {
            int gj = j0 + jg * 4 + jj;
            float ci = g_cinv[((size_t)b * NNT + gi) * NNT + gj];
            size_t base = (((size_t)b * NNT + gi) * NNT + gj) * HHT + h0 + hg * 2;
            float a0, a1;
            UNPACK2(a0, a1, acc2[ii][jj]);
            float2 v;
            v.x = a0 * ci;
            v.y = a1 * ci;
            *(float2*)&g_outer[base] = v;
        }
    }
}

// ---------------- kernel 5: final GEMM  (131072 x 256) @ (256 x 256) + bo ---
__global__ void __launch_bounds__(256) final_kernel(const float* __restrict__ Wo,
                                                    const float* __restrict__ bo,
                                                    float* __restrict__ out) {
    __shared__ __align__(16) float As[16][132];
    __shared__ __align__(16) float Bs[16][128];

    int tid = threadIdx.x;
    int tx = tid & 15, ty = tid >> 4;
    int r0 = blockIdx.y * 128;   // bij row tile
    int n0 = blockIdx.x * 128;   // d tile

    u64 acc2[8][4];
#pragma unroll
    for (int i = 0; i < 8; i++)
#pragma unroll
        for (int j = 0; j < 4; j++) acc2[i][j] = 0ULL;

    for (int kb = 0; kb < HHT; kb += 16) {
#pragma unroll
        for (int it = 0; it < 2; it++) {
            int f = it * 256 + tid;
            int row = f >> 2, kv = f & 3;
            float4 v = *(const float4*)&g_outer[(size_t)(r0 + row) * HHT + kb + kv * 4];
            As[kv * 4 + 0][row] = v.x;
            As[kv * 4 + 1][row] = v.y;
            As[kv * 4 + 2][row] = v.z;
            As[kv * 4 + 3][row] = v.w;
        }
#pragma unroll
        for (int it = 0; it < 2; it++) {
            int f = it * 256 + tid;
            int k = f >> 5, nv = f & 31;
            *(float4*)&Bs[k][nv * 4] =
                *(const float4*)&Wo[(size_t)(kb + k) * DDT + n0 + nv * 4];
        }
        __syncthreads();
#pragma unroll
        for (int k = 0; k < 16; k++) {
            float4 a0 = *(const float4*)&As[k][ty * 8];
            float4 a1 = *(const float4*)&As[k][ty * 8 + 4];
            const u64* bp = (const u64*)&Bs[k][tx * 8];
            u64 b0 = bp[0], b1 = bp[1], b2 = bp[2], b3 = bp[3];
            float av[8] = {a0.x, a0.y, a0.z, a0.w, a1.x, a1.y, a1.z, a1.w};
            u64 aa[8];
#pragma unroll
            for (int i = 0; i < 8; i++) PACK2(aa[i], av[i], av[i]);
#pragma unroll
            for (int i = 0; i < 8; i++) {
                FMA2(acc2[i][0], aa[i], b0, acc2[i][0]);
                FMA2(acc2[i][1], aa[i], b1, acc2[i][1]);
                FMA2(acc2[i][2], aa[i], b2, acc2[i][2]);
                FMA2(acc2[i][3], aa[i], b3, acc2[i][3]);
            }
        }
        __syncthreads();
    }

    float bb[8];
#pragma unroll
    for (int j = 0; j < 8; j++) bb[j] = bo[n0 + tx * 8 + j];

#pragma unroll
    for (int i = 0; i < 8; i++) {
        size_t row = (size_t)(r0 + ty * 8 + i);
#pragma unroll
        for (int jv = 0; jv < 2; jv++) {
            float c0, c1, c2, c3;
            UNPACK2(c0, c1, acc2[i][jv * 2 + 0]);
            UNPACK2(c2, c3, acc2[i][jv * 2 + 1]);
            float4 v;
            v.x = c0 + bb[jv * 4 + 0];
            v.y = c1 + bb[jv * 4 + 1];
            v.z = c2 + bb[jv * 4 + 2];
            v.w = c3 + bb[jv * 4 + 3];
            *(float4*)&out[row * DDT + n0 + tx * 8 + jv * 4] = v;
        }
    }
}

// ---------------- launch ------------------------------------------------------
extern "C" void kernel_launch(void* const* d_in, const int* in_sizes, int n_in,
                              void* d_out, int out_size) {
    // metadata order: x, mask, ln_w, ln_b, Wl, bl, Wr, br, Wo, bo
    const float* x    = (const float*)d_in[0];
    const void*  mask = d_in[1];
    const float* ln_w = (const float*)d_in[2];
    const float* ln_b = (const float*)d_in[3];
    const float* Wl   = (const float*)d_in[4];
    const float* bl   = (const float*)d_in[5];
    const float* Wr   = (const float*)d_in[6];
    const float* br   = (const float*)d_in[7];
    const float* Wo   = (const float*)d_in[8];
    const float* bo   = (const float*)d_in[9];
    float* out = (float*)d_out;

    detect_mask_kernel<<<1, 256>>>((const unsigned int*)mask);
    expand_mask_kernel<<<ROWS / 256, 256>>>(mask);
    ln_kernel<<<ROWS, 256>>>(x, ln_w, ln_b);
    proj_kernel<<<dim3(HHT / 128, ROWS / 128, 2), 256>>>(Wl, bl, Wr, br);
    cnt_kernel<<<BB * NNT, 256>>>();
    outer_kernel<<<dim3(HHT / 8, NNT / 32, BB * (NNT / 64)), 256>>>();
    final_kernel<<<dim3(DDT / 128, (BB * NNT * NNT) / 128), 256>>>(Wo, bo, out);
}

// round 8
// speedup vs baseline: 1.6394x; 1.6394x over previous
#include <cuda_runtime.h>
#include <cuda_bf16.h>
#include <cstdint>
#include <cstddef>

// Problem constants (fixed by the reference setup)
#define BB   2
#define MMT  64     // m (outer-mean dim)
#define NNT  256    // i / j
#define DDT  256    // d
#define HHT  256    // h
#define ROWS (BB*MMT*NNT)                 // 32768 token rows (b,m,i)
#define PAIRROWS ((size_t)BB*NNT*NNT)     // 131072 pair rows (b,i,j)

typedef unsigned int u32;
typedef unsigned long long u64;

// ---------------- scratch (device globals; no allocations allowed) ----------
// bf16 hi/lo pair words: low 16 bits = hi, high 16 bits = lo
__device__ u32   g_xnp[(size_t)ROWS * DDT];        // 33.5 MB  layernormed x (pairs)
__device__ float g_L [(size_t)ROWS * HHT];         // 33.5 MB  left  proj (masked, fp32)
__device__ float g_R [(size_t)ROWS * HHT];         // 33.5 MB  right proj (masked, fp32)
__device__ u32   g_outp[PAIRROWS * HHT];           // 134  MB  outer pairs [b,i,j][h]
__device__ u32   g_Wp[3][DDT * HHT];               // W^T pairs: [w][n*256+k] 0=Wl 1=Wr 2=Wo
__device__ float g_maskf[ROWS];
__device__ float g_cinv[BB * NNT * NNT];
__device__ int   g_mask_mode;

// ---------------- helpers -----------------------------------------------------
__device__ __forceinline__ u32 smem_u32(const void* p) {
    u32 a;
    asm("{ .reg .u64 t; cvta.to.shared.u64 t, %1; cvt.u32.u64 %0, t; }"
        : "=r"(a) : "l"(p));
    return a;
}

__device__ __forceinline__ u32 pack_pair(float v) {
    __nv_bfloat16 h = __float2bfloat16(v);
    __nv_bfloat16 l = __float2bfloat16(v - __bfloat162float(h));
    return (u32)__bfloat16_as_ushort(h) | ((u32)__bfloat16_as_ushort(l) << 16);
}

__device__ __forceinline__ void ldsm4(u32 r[4], u32 addr) {
    asm volatile("ldmatrix.sync.aligned.m8n8.x4.shared.b16 {%0,%1,%2,%3}, [%4];"
                 : "=r"(r[0]), "=r"(r[1]), "=r"(r[2]), "=r"(r[3]) : "r"(addr));
}

__device__ __forceinline__ void mma_bf16(float d[4], const u32 a[4], const u32 b0,
                                         const u32 b1) {
    asm volatile(
        "mma.sync.aligned.m16n8k16.row.col.f32.bf16.bf16.f32 "
        "{%0,%1,%2,%3}, {%4,%5,%6,%7}, {%8,%9}, {%0,%1,%2,%3};"
        : "+f"(d[0]), "+f"(d[1]), "+f"(d[2]), "+f"(d[3])
        : "r"(a[0]), "r"(a[1]), "r"(a[2]), "r"(a[3]), "r"(b0), "r"(b1));
}

// ---------------- kernel 0a: detect mask dtype -------------------------------
__global__ void detect_mask_kernel(const u32* p) {
    __shared__ int s_nonbin, s_nonfp;
    if (threadIdx.x == 0) { s_nonbin = 0; s_nonfp = 0; }
    __syncthreads();
    int nonbin = 0, nonfp = 0;
    for (int idx = threadIdx.x; idx < 8192; idx += 256) {
        u32 v = p[idx];
        if (v != 0u && v != 1u)           nonbin = 1;
        if (v != 0u && v != 0x3F800000u)  nonfp  = 1;
    }
    if (nonbin) atomicOr(&s_nonbin, 1);
    if (nonfp)  atomicOr(&s_nonfp, 1);
    __syncthreads();
    if (threadIdx.x == 0) {
        int mode;
        if      (!s_nonbin) mode = 0;
        else if (!s_nonfp)  mode = 1;
        else                mode = 2;
        g_mask_mode = mode;
    }
}

// ---------------- kernel 0b: expand mask to float ----------------------------
__global__ void expand_mask_kernel(const void* p) {
    int r = blockIdx.x * 256 + threadIdx.x;
    int mode = g_mask_mode;
    float f;
    if (mode == 0)      f = (((const int*)p)[r]           != 0)    ? 1.0f : 0.0f;
    else if (mode == 1) f = (((const float*)p)[r]         != 0.0f) ? 1.0f : 0.0f;
    else                f = (((const unsigned char*)p)[r] != 0)    ? 1.0f : 0.0f;
    g_maskf[r] = f;
}

// ---------------- kernel 0c: transpose + split weights into bf16 pairs -------
__global__ void wsplit_kernel(const float* __restrict__ Wl,
                              const float* __restrict__ Wr,
                              const float* __restrict__ Wo) {
    int idx = blockIdx.x * 256 + threadIdx.x;   // 0 .. 3*65536-1
    int w = idx >> 16;
    int r = idx & 65535;
    int n = r >> 8, k = r & 255;
    const float* W = (w == 0) ? Wl : ((w == 1) ? Wr : Wo);
    g_Wp[w][n * 256 + k] = pack_pair(W[k * 256 + n]);
}

// ---------------- kernel 1: LayerNorm -> bf16 pair words ---------------------
__global__ void __launch_bounds__(256) ln_kernel(const float* __restrict__ x,
                                                 const float* __restrict__ w,
                                                 const float* __restrict__ bvec) {
    __shared__ float red[256];
    __shared__ float s_mu, s_rstd;
    int row = blockIdx.x;
    int t = threadIdx.x;
    float v = x[(size_t)row * DDT + t];
    red[t] = v;
    __syncthreads();
    for (int s = 128; s > 0; s >>= 1) {
        if (t < s) red[t] += red[t + s];
        __syncthreads();
    }
    if (t == 0) s_mu = red[0] * (1.0f / DDT);
    __syncthreads();
    float mu = s_mu;
    float dv = v - mu;
    red[t] = dv * dv;
    __syncthreads();
    for (int s = 128; s > 0; s >>= 1) {
        if (t < s) red[t] += red[t + s];
        __syncthreads();
    }
    if (t == 0) s_rstd = rsqrtf(red[0] * (1.0f / DDT) + 1e-5f);
    __syncthreads();
    g_xnp[(size_t)row * DDT + t] = pack_pair(dv * s_rstd * w[t] + bvec[t]);
}

// ---------------- kernel 2: bf16-split tensor-core GEMM ----------------------
// D[row][n] = sum_k A[row][k] * Wt[n][k], split into hi*hi + hi*lo + lo*hi.
// CTA tile 128(M) x 128(N), k-chunk 32, 8 warps (2M x 4N), warp tile 64x32.
// mode 0: A=g_xnp, B=Wl/Wr by blockIdx.z, epilogue (acc+bias)*mask -> g_L/g_R
// mode 1: A=g_outp, B=Wo,              epilogue  acc+bo          -> out
#define RSTRIDE 80                       // bytes per 32-bf16 shared row (+16 pad)
#define AHI 0
#define ALO (128*RSTRIDE)                // 10240
#define BHI (2*128*RSTRIDE)              // 20480
#define BLO (3*128*RSTRIDE)              // 30720
#define SMEM_MM (4*128*RSTRIDE)          // 40960

__global__ void __launch_bounds__(256) mm_kernel(int mode,
                                                 const float* __restrict__ bias_l,
                                                 const float* __restrict__ bias_r,
                                                 float* __restrict__ OutExt) {
    __shared__ __align__(16) char sm[SMEM_MM];

    const int tid  = threadIdx.x;
    const int lane = tid & 31;
    const int wid  = tid >> 5;
    const int r0   = blockIdx.y * 128;            // M tile
    const int n0g  = blockIdx.x * 128;            // N tile
    const int m0w  = (wid >> 2) * 64;             // warp M offset in tile
    const int n0w  = (wid & 3) * 32;              // warp N offset in tile

    const u32* Ap; const u32* Bp; const float* bias; float* Out; bool use_mask;
    if (mode == 0) {
        Ap = g_xnp;
        if (blockIdx.z == 0) { Bp = g_Wp[0]; bias = bias_l; Out = g_L; }
        else                 { Bp = g_Wp[1]; bias = bias_r; Out = g_R; }
        use_mask = true;
    } else {
        Ap = g_outp; Bp = g_Wp[2]; bias = bias_l; Out = OutExt; use_mask = false;
    }

    const u32 smem = smem_u32(sm);

    // per-lane ldmatrix base offsets (bytes)
    const u32 aOff = (u32)((lane & 15) * RSTRIDE + (lane >> 4) * 16);
    const u32 bOff = (u32)(((lane & 7) + ((lane >> 4) & 1) * 8) * RSTRIDE +
                           ((lane >> 3) & 1) * 16);

    float acc[4][4][4];
#pragma unroll
    for (int mt = 0; mt < 4; mt++)
#pragma unroll
        for (int nt = 0; nt < 4; nt++)
#pragma unroll
            for (int q = 0; q < 4; q++) acc[mt][nt][q] = 0.0f;

    const int srow = tid >> 1;          // 0..127
    const int shalf = tid & 1;          // which 16-elem half of the 32-k chunk

    for (int c = 0; c < 8; c++) {       // K = 256 in chunks of 32
        // ---- stage A and B (hi/lo split via byte-perm) ----
        {
            const uint4* ga = (const uint4*)&Ap[(size_t)(r0 + srow) * 256 + c * 32 + shalf * 16];
            const uint4* gb = (const uint4*)&Bp[(size_t)(n0g + srow) * 256 + c * 32 + shalf * 16];
            u32 rbase = (u32)(srow * RSTRIDE + shalf * 32);
#pragma unroll
            for (int q = 0; q < 4; q++) {
                uint4 va = ga[q];
                u32 h01 = __byte_perm(va.x, va.y, 0x5410);
                u32 h23 = __byte_perm(va.z, va.w, 0x5410);
                u32 l01 = __byte_perm(va.x, va.y, 0x7632);
                u32 l23 = __byte_perm(va.z, va.w, 0x7632);
                *(u64*)(sm + AHI + rbase + q * 8) = (u64)h01 | ((u64)h23 << 32);
                *(u64*)(sm + ALO + rbase + q * 8) = (u64)l01 | ((u64)l23 << 32);
                uint4 vb = gb[q];
                h01 = __byte_perm(vb.x, vb.y, 0x5410);
                h23 = __byte_perm(vb.z, vb.w, 0x5410);
                l01 = __byte_perm(vb.x, vb.y, 0x7632);
                l23 = __byte_perm(vb.z, vb.w, 0x7632);
                *(u64*)(sm + BHI + rbase + q * 8) = (u64)h01 | ((u64)h23 << 32);
                *(u64*)(sm + BLO + rbase + q * 8) = (u64)l01 | ((u64)l23 << 32);
            }
        }
        __syncthreads();

        // ---- compute: 2 k16 sub-steps ----
#pragma unroll
        for (int s = 0; s < 2; s++) {
            const u32 kbyte = (u32)(s * 32);
            // B fragments: 4 n8 tiles, hi and lo
            u32 bhi[8], blo[8];
#pragma unroll
            for (int ntp = 0; ntp < 2; ntp++) {
                u32 ad = smem + (u32)BHI + (u32)((n0w + ntp * 16) * RSTRIDE) + kbyte + bOff;
                ldsm4(&bhi[ntp * 4], ad);
                ad = smem + (u32)BLO + (u32)((n0w + ntp * 16) * RSTRIDE) + kbyte + bOff;
                ldsm4(&blo[ntp * 4], ad);
            }
#pragma unroll
            for (int mt = 0; mt < 4; mt++) {
                u32 ahi[4], alo[4];
                u32 ad = smem + (u32)AHI + (u32)((m0w + mt * 16) * RSTRIDE) + kbyte + aOff;
                ldsm4(ahi, ad);
                ad = smem + (u32)ALO + (u32)((m0w + mt * 16) * RSTRIDE) + kbyte + aOff;
                ldsm4(alo, ad);
#pragma unroll
                for (int nt = 0; nt < 4; nt++) {
                    const u32* bh = &bhi[(nt >> 1) * 4 + (nt & 1) * 2];
                    const u32* bl = &blo[(nt >> 1) * 4 + (nt & 1) * 2];
                    mma_bf16(acc[mt][nt], ahi, bh[0], bh[1]);
                    mma_bf16(acc[mt][nt], ahi, bl[0], bl[1]);
                    mma_bf16(acc[mt][nt], alo, bh[0], bh[1]);
                }
            }
        }
        __syncthreads();
    }

    // ---- epilogue ----
#pragma unroll
    for (int mt = 0; mt < 4; mt++) {
        int rA = r0 + m0w + mt * 16 + (lane >> 2);
        int rB = rA + 8;
        float mfA = 1.0f, mfB = 1.0f;
        if (use_mask) { mfA = g_maskf[rA]; mfB = g_maskf[rB]; }
#pragma unroll
        for (int nt = 0; nt < 4; nt++) {
            int n = n0g + n0w + nt * 8 + (lane & 3) * 2;
            float b0 = bias[n], b1 = bias[n + 1];
            float2 v0, v1;
            v0.x = (acc[mt][nt][0] + b0) * mfA;
            v0.y = (acc[mt][nt][1] + b1) * mfA;
            v1.x = (acc[mt][nt][2] + b0) * mfB;
            v1.y = (acc[mt][nt][3] + b1) * mfB;
            *(float2*)&Out[(size_t)rA * 256 + n] = v0;
            *(float2*)&Out[(size_t)rB * 256 + n] = v1;
        }
    }
}

// ---------------- kernel 3: pair-count inverse -------------------------------
__global__ void __launch_bounds__(256) cnt_kernel() {
    int b = blockIdx.x >> 8;
    int i = blockIdx.x & 255;
    int j = threadIdx.x;
    __shared__ float mi[MMT];
    if (j < MMT) mi[j] = g_maskf[(b * MMT + j) * NNT + i];
    __syncthreads();
    float s = 0.0f;
#pragma unroll 8
    for (int m = 0; m < MMT; m++)
        s = fmaf(mi[m], g_maskf[(b * MMT + m) * NNT + j], s);
    g_cinv[((size_t)b * NNT + i) * NNT + j] = 1.0f / ((float)MMT * (s + 1e-5f));
}

// ---------------- kernel 4: masked outer-mean contraction over m -------------
// outer[b][i][j][h] = cinv[b][i][j] * sum_m L[b,m,i,h] * R[b,m,j,h]
// (proven fp32 SIMT version; epilogue writes bf16 pair words for final GEMM)
__global__ void __launch_bounds__(256) outer_kernel() {
    __shared__ __align__(16) float Ls[8][8][68];  // [m][h][i] (+4 pad)
    __shared__ __align__(16) float Rs[8][8][32];  // [m][h][j]

    int tid = threadIdx.x;
    int hb = blockIdx.x;
    int jb = blockIdx.y;
    int zb = blockIdx.z;
    int b  = zb >> 2;
    int i0 = (zb & 3) * 64;
    int j0 = jb * 32;
    int h0 = hb * 8;

    int jg = tid & 7;
    int hg = (tid >> 3) & 3;
    int ig = tid >> 5;

    float acc[8][4][2];
#pragma unroll
    for (int ii = 0; ii < 8; ii++)
#pragma unroll
        for (int jj = 0; jj < 4; jj++) { acc[ii][jj][0] = 0.0f; acc[ii][jj][1] = 0.0f; }

    for (int mc = 0; mc < MMT; mc += 8) {
#pragma unroll
        for (int it = 0; it < 4; it++) {
            int f = it * 256 + tid;
            int hv = f & 1;
            int li = (f >> 1) & 63;
            int lm = f >> 7;
            float4 v = *(const float4*)
                &g_L[(((size_t)(b * MMT + mc + lm) * NNT + i0 + li) * HHT) + h0 + hv * 4];
            Ls[lm][hv * 4 + 0][li] = v.x;
            Ls[lm][hv * 4 + 1][li] = v.y;
            Ls[lm][hv * 4 + 2][li] = v.z;
            Ls[lm][hv * 4 + 3][li] = v.w;
        }
#pragma unroll
        for (int it = 0; it < 2; it++) {
            int f = it * 256 + tid;
            int hv = f & 1;
            int lj = (f >> 1) & 31;
            int lm = f >> 6;
            float4 v = *(const float4*)
                &g_R[(((size_t)(b * MMT + mc + lm) * NNT + j0 + lj) * HHT) + h0 + hv * 4];
            Rs[lm][hv * 4 + 0][lj] = v.x;
            Rs[lm][hv * 4 + 1][lj] = v.y;
            Rs[lm][hv * 4 + 2][lj] = v.z;
            Rs[lm][hv * 4 + 3][lj] = v.w;
        }
        __syncthreads();
#pragma unroll
        for (int lm = 0; lm < 8; lm++) {
            float4 l00 = *(const float4*)&Ls[lm][hg * 2 + 0][ig * 8];
            float4 l01 = *(const float4*)&Ls[lm][hg * 2 + 0][ig * 8 + 4];
            float4 l10 = *(const float4*)&Ls[lm][hg * 2 + 1][ig * 8];
            float4 l11 = *(const float4*)&Ls[lm][hg * 2 + 1][ig * 8 + 4];
            float4 r0v = *(const float4*)&Rs[lm][hg * 2 + 0][jg * 4];
            float4 r1v = *(const float4*)&Rs[lm][hg * 2 + 1][jg * 4];
            float lv0[8] = {l00.x, l00.y, l00.z, l00.w, l01.x, l01.y, l01.z, l01.w};
            float lv1[8] = {l10.x, l10.y, l10.z, l10.w, l11.x, l11.y, l11.z, l11.w};
            float rv0[4] = {r0v.x, r0v.y, r0v.z, r0v.w};
            float rv1[4] = {r1v.x, r1v.y, r1v.z, r1v.w};
#pragma unroll
            for (int ii = 0; ii < 8; ii++)
#pragma unroll
                for (int jj = 0; jj < 4; jj++) {
                    acc[ii][jj][0] = fmaf(lv0[ii], rv0[jj], acc[ii][jj][0]);
                    acc[ii][jj][1] = fmaf(lv1[ii], rv1[jj], acc[ii][jj][1]);
                }
        }
        __syncthreads();
    }

#pragma unroll
    for (int ii = 0; ii < 8; ii++) {
        int gi = i0 + ig * 8 + ii;
#pragma unroll
        for (int jj = 0; jj < 4; jj++) {
            int gj = j0 + jg * 4 + jj;
            float ci = g_cinv[((size_t)b * NNT + gi) * NNT + gj];
            size_t base = (((size_t)b * NNT + gi) * NNT + gj) * HHT + h0 + hg * 2;
            uint2 pv;
            pv.x = pack_pair(acc[ii][jj][0] * ci);
            pv.y = pack_pair(acc[ii][jj][1] * ci);
            *(uint2*)&g_outp[base] = pv;
        }
    }
}

// ---------------- launch ------------------------------------------------------
extern "C" void kernel_launch(void* const* d_in, const int* in_sizes, int n_in,
                              void* d_out, int out_size) {
    // metadata order: x, mask, ln_w, ln_b, Wl, bl, Wr, br, Wo, bo
    const float* x    = (const float*)d_in[0];
    const void*  mask = d_in[1];
    const float* ln_w = (const float*)d_in[2];
    const float* ln_b = (const float*)d_in[3];
    const float* Wl   = (const float*)d_in[4];
    const float* bl   = (const float*)d_in[5];
    const float* Wr   = (const float*)d_in[6];
    const float* br   = (const float*)d_in[7];
    const float* Wo   = (const float*)d_in[8];
    const float* bo   = (const float*)d_in[9];
    float* out = (float*)d_out;
    (void)Wl; (void)Wr; (void)Wo;

    detect_mask_kernel<<<1, 256>>>((const u32*)mask);
    expand_mask_kernel<<<ROWS / 256, 256>>>(mask);
    wsplit_kernel<<<768, 256>>>(Wl, Wr, Wo);
    ln_kernel<<<ROWS, 256>>>(x, ln_w, ln_b);
    cnt_kernel<<<BB * NNT, 256>>>();
    // projections: L and R (blockIdx.z selects)
    mm_kernel<<<dim3(2, ROWS / 128, 2), 256>>>(0, bl, br, nullptr);
    outer_kernel<<<dim3(HHT / 8, NNT / 32, BB * (NNT / 64)), 256>>>();
    // final GEMM: pair rows x Wo + bo
    mm_kernel<<<dim3(2, (int)(PAIRROWS / 128), 1), 256>>>(1, bo, nullptr, out);
}

// round 9
// speedup vs baseline: 1.6739x; 1.0211x over previous
#include <cuda_runtime.h>
#include <cuda_bf16.h>
#include <cstdint>
#include <cstddef>

// Problem constants (fixed by the reference setup)
#define BB   2
#define MMT  64     // m (outer-mean dim)
#define NNT  256    // i / j
#define DDT  256    // d
#define HHT  256    // h
#define ROWS (BB*MMT*NNT)                 // 32768 token rows (b,m,i)
#define PAIRROWS ((size_t)BB*NNT*NNT)     // 131072 pair rows (b,i,j)

typedef unsigned int u32;
typedef unsigned long long u64;
typedef __nv_bfloat16 bf16;

// ---------------- scratch (device globals; no allocations allowed) ----------
// hi/lo bf16 planes (separate arrays -> cp.async staging needs no splitting)
__device__ __align__(16) bf16  g_xh[(size_t)ROWS * DDT];   // 16.8 MB
__device__ __align__(16) bf16  g_xl[(size_t)ROWS * DDT];   // 16.8 MB
__device__ __align__(16) float g_L [(size_t)ROWS * HHT];   // 33.5 MB (masked, fp32)
__device__ __align__(16) float g_R [(size_t)ROWS * HHT];   // 33.5 MB
__device__ __align__(16) bf16  g_oh[PAIRROWS * HHT];       // 67 MB outer hi
__device__ __align__(16) bf16  g_ol[PAIRROWS * HHT];       // 67 MB outer lo
__device__ __align__(16) bf16  g_Wh[3][DDT * HHT];         // W^T hi: [w][n*256+k]
__device__ __align__(16) bf16  g_Wlo[3][DDT * HHT];        // W^T lo  (0=Wl 1=Wr 2=Wo)
__device__ float g_maskf[ROWS];
__device__ float g_cinv[BB * NNT * NNT];
__device__ int   g_mask_mode;

// ---------------- helpers -----------------------------------------------------
__device__ __forceinline__ u32 smem_u32(const void* p) {
    u32 a;
    asm("{ .reg .u64 t; cvta.to.shared.u64 t, %1; cvt.u32.u64 %0, t; }"
        : "=r"(a) : "l"(p));
    return a;
}

#define CP16(dst, src) \
    asm volatile("cp.async.ca.shared.global [%0], [%1], 16;" :: "r"(dst), "l"(src))
#define CPCOMMIT() asm volatile("cp.async.commit_group;" ::: "memory")
#define CPWAIT(n)  asm volatile("cp.async.wait_group %0;" :: "n"(n) : "memory")

__device__ __forceinline__ void ldsm4(u32 r[4], u32 addr) {
    asm volatile("ldmatrix.sync.aligned.m8n8.x4.shared.b16 {%0,%1,%2,%3}, [%4];"
                 : "=r"(r[0]), "=r"(r[1]), "=r"(r[2]), "=r"(r[3]) : "r"(addr));
}

__device__ __forceinline__ void mma_bf16(float d[4], const u32 a[4], const u32 b0,
                                         const u32 b1) {
    asm volatile(
        "mma.sync.aligned.m16n8k16.row.col.f32.bf16.bf16.f32 "
        "{%0,%1,%2,%3}, {%4,%5,%6,%7}, {%8,%9}, {%0,%1,%2,%3};"
        : "+f"(d[0]), "+f"(d[1]), "+f"(d[2]), "+f"(d[3])
        : "r"(a[0]), "r"(a[1]), "r"(a[2]), "r"(a[3]), "r"(b0), "r"(b1));
}

__device__ __forceinline__ u32 pack2h(float a, float b) {
    // two bf16 "hi" values packed into one u32
    return (u32)__bfloat16_as_ushort(__float2bfloat16(a)) |
           ((u32)__bfloat16_as_ushort(__float2bfloat16(b)) << 16);
}

// ---------------- kernel 0a: detect mask dtype -------------------------------
__global__ void detect_mask_kernel(const u32* p) {
    __shared__ int s_nonbin, s_nonfp;
    if (threadIdx.x == 0) { s_nonbin = 0; s_nonfp = 0; }
    __syncthreads();
    int nonbin = 0, nonfp = 0;
    for (int idx = threadIdx.x; idx < 8192; idx += 256) {
        u32 v = p[idx];
        if (v != 0u && v != 1u)           nonbin = 1;
        if (v != 0u && v != 0x3F800000u)  nonfp  = 1;
    }
    if (nonbin) atomicOr(&s_nonbin, 1);
    if (nonfp)  atomicOr(&s_nonfp, 1);
    __syncthreads();
    if (threadIdx.x == 0) {
        int mode;
        if      (!s_nonbin) mode = 0;
        else if (!s_nonfp)  mode = 1;
        else                mode = 2;
        g_mask_mode = mode;
    }
}

// ---------------- kernel 0b: expand mask to float ----------------------------
__global__ void expand_mask_kernel(const void* p) {
    int r = blockIdx.x * 256 + threadIdx.x;
    int mode = g_mask_mode;
    float f;
    if (mode == 0)      f = (((const int*)p)[r]           != 0)    ? 1.0f : 0.0f;
    else if (mode == 1) f = (((const float*)p)[r]         != 0.0f) ? 1.0f : 0.0f;
    else                f = (((const unsigned char*)p)[r] != 0)    ? 1.0f : 0.0f;
    g_maskf[r] = f;
}

// ---------------- kernel 0c: transpose + split weights into planes -----------
__global__ void wsplit_kernel(const float* __restrict__ Wl,
                              const float* __restrict__ Wr,
                              const float* __restrict__ Wo) {
    int idx = blockIdx.x * 256 + threadIdx.x;   // 0 .. 3*65536-1
    int w = idx >> 16;
    int r = idx & 65535;
    int n = r >> 8, k = r & 255;
    const float* W = (w == 0) ? Wl : ((w == 1) ? Wr : Wo);
    float v = W[k * 256 + n];
    bf16 h = __float2bfloat16(v);
    g_Wh[w][n * 256 + k]  = h;
    g_Wlo[w][n * 256 + k] = __float2bfloat16(v - __bfloat162float(h));
}

// ---------------- kernel 1: LayerNorm (warp per row) -> bf16 planes ----------
__global__ void __launch_bounds__(256) ln_kernel(const float* __restrict__ x,
                                                 const float* __restrict__ w,
                                                 const float* __restrict__ bvec) {
    int lane = threadIdx.x & 31;
    int warp = threadIdx.x >> 5;
    int row  = blockIdx.x * 8 + warp;

    const float4* xr = (const float4*)&x[(size_t)row * DDT];
    float4 v0 = xr[lane * 2];
    float4 v1 = xr[lane * 2 + 1];

    float s  = v0.x + v0.y + v0.z + v0.w + v1.x + v1.y + v1.z + v1.w;
    float sq = v0.x * v0.x + v0.y * v0.y + v0.z * v0.z + v0.w * v0.w +
               v1.x * v1.x + v1.y * v1.y + v1.z * v1.z + v1.w * v1.w;
#pragma unroll
    for (int o = 16; o > 0; o >>= 1) {
        s  += __shfl_xor_sync(0xFFFFFFFFu, s,  o);
        sq += __shfl_xor_sync(0xFFFFFFFFu, sq, o);
    }
    float mu   = s * (1.0f / DDT);
    float var  = sq * (1.0f / DDT) - mu * mu;
    float rstd = rsqrtf(var + 1e-5f);

    const float4* wr = (const float4*)w;
    const float4* br = (const float4*)bvec;
    float4 w0 = wr[lane * 2], w1 = wr[lane * 2 + 1];
    float4 b0 = br[lane * 2], b1 = br[lane * 2 + 1];

    float y[8];
    y[0] = (v0.x - mu) * rstd * w0.x + b0.x;
    y[1] = (v0.y - mu) * rstd * w0.y + b0.y;
    y[2] = (v0.z - mu) * rstd * w0.z + b0.z;
    y[3] = (v0.w - mu) * rstd * w0.w + b0.w;
    y[4] = (v1.x - mu) * rstd * w1.x + b1.x;
    y[5] = (v1.y - mu) * rstd * w1.y + b1.y;
    y[6] = (v1.z - mu) * rstd * w1.z + b1.z;
    y[7] = (v1.w - mu) * rstd * w1.w + b1.w;

    uint4 hv, lv;
    float r0, r1;
    hv.x = pack2h(y[0], y[1]);
    r0 = y[0] - __bfloat162float(__float2bfloat16(y[0]));
    r1 = y[1] - __bfloat162float(__float2bfloat16(y[1]));
    lv.x = pack2h(r0, r1);
    hv.y = pack2h(y[2], y[3]);
    r0 = y[2] - __bfloat162float(__float2bfloat16(y[2]));
    r1 = y[3] - __bfloat162float(__float2bfloat16(y[3]));
    lv.y = pack2h(r0, r1);
    hv.z = pack2h(y[4], y[5]);
    r0 = y[4] - __bfloat162float(__float2bfloat16(y[4]));
    r1 = y[5] - __bfloat162float(__float2bfloat16(y[5]));
    lv.z = pack2h(r0, r1);
    hv.w = pack2h(y[6], y[7]);
    r0 = y[6] - __bfloat162float(__float2bfloat16(y[6]));
    r1 = y[7] - __bfloat162float(__float2bfloat16(y[7]));
    lv.w = pack2h(r0, r1);

    *(uint4*)&g_xh[(size_t)row * DDT + lane * 8] = hv;
    *(uint4*)&g_xl[(size_t)row * DDT + lane * 8] = lv;
}

// ---------------- kernel 2: bf16-split tensor-core GEMM (cp.async 2-stage) ---
// D[row][n] = sum_k A[row][k] * Wt[n][k], hi*hi + hi*lo + lo*hi.
// CTA tile 128(M)x128(N), K-chunk 16, double-buffered, 8 warps (2M x 4N).
#define RSTRIDE 48                        // bytes per 16-bf16 shared row (+16 pad)
#define PLANE   (128 * RSTRIDE)           // 6144
#define BUFSZ   (4 * PLANE)               // 24576
#define AHI 0
#define ALO PLANE
#define BHI (2 * PLANE)
#define BLO (3 * PLANE)

__global__ void __launch_bounds__(256) mm_kernel(int mode,
                                                 const float* __restrict__ bias_l,
                                                 const float* __restrict__ bias_r,
                                                 float* __restrict__ OutExt) {
    __shared__ __align__(16) char sm[2 * BUFSZ];   // 48 KB static

    const int tid  = threadIdx.x;
    const int lane = tid & 31;
    const int wid  = tid >> 5;
    const int r0   = blockIdx.y * 128;            // M tile
    const int n0g  = blockIdx.x * 128;            // N tile
    const int m0w  = (wid >> 2) * 64;
    const int n0w  = (wid & 3) * 32;

    const bf16* Ah; const bf16* Al; const bf16* Bh; const bf16* Bl;
    const float* bias; float* Out; bool use_mask;
    if (mode == 0) {
        Ah = g_xh; Al = g_xl;
        if (blockIdx.z == 0) { Bh = g_Wh[0]; Bl = g_Wlo[0]; bias = bias_l; Out = g_L; }
        else                 { Bh = g_Wh[1]; Bl = g_Wlo[1]; bias = bias_r; Out = g_R; }
        use_mask = true;
    } else {
        Ah = g_oh; Al = g_ol; Bh = g_Wh[2]; Bl = g_Wlo[2];
        bias = bias_l; Out = OutExt; use_mask = false;
    }

    const u32 smem = smem_u32(sm);
    // staging task: row = tid>>1 (0..127), seg = tid&1 (two 16B halves of 32B row)
    const int srow = tid >> 1;
    const int sseg = tid & 1;
    const u32 sdst = (u32)(srow * RSTRIDE + sseg * 16);
    const size_t arow = (size_t)(r0 + srow) * 256 + sseg * 8;
    const size_t brow = (size_t)(n0g + srow) * 256 + sseg * 8;

    // per-lane ldmatrix base offsets (bytes)
    const u32 aOff = (u32)((lane & 15) * RSTRIDE + (lane >> 4) * 16);
    const u32 bOff = (u32)(((lane & 7) + ((lane >> 4) & 1) * 8) * RSTRIDE +
                           ((lane >> 3) & 1) * 16);

    float acc[4][4][4];
#pragma unroll
    for (int mt = 0; mt < 4; mt++)
#pragma unroll
        for (int nt = 0; nt < 4; nt++)
#pragma unroll
            for (int q = 0; q < 4; q++) acc[mt][nt][q] = 0.0f;

    // ---- stage chunk 0 into buffer 0 ----
    {
        u32 base = smem;
        CP16(base + AHI + sdst, Ah + arow);
        CP16(base + ALO + sdst, Al + arow);
        CP16(base + BHI + sdst, Bh + brow);
        CP16(base + BLO + sdst, Bl + brow);
        CPCOMMIT();
    }

    for (int c = 0; c < 16; c++) {
        if (c + 1 < 16) {
            u32 base = smem + (u32)(((c + 1) & 1) * BUFSZ);
            size_t koff = (size_t)(c + 1) * 16;
            CP16(base + AHI + sdst, Ah + arow + koff);
            CP16(base + ALO + sdst, Al + arow + koff);
            CP16(base + BHI + sdst, Bh + brow + koff);
            CP16(base + BLO + sdst, Bl + brow + koff);
            CPCOMMIT();
            CPWAIT(1);
        } else {
            CPWAIT(0);
        }
        __syncthreads();

        const u32 cb = smem + (u32)((c & 1) * BUFSZ);
        // B fragments: 4 n8 tiles, hi and lo
        u32 bhi[8], blo[8];
#pragma unroll
        for (int ntp = 0; ntp < 2; ntp++) {
            ldsm4(&bhi[ntp * 4], cb + BHI + (u32)((n0w + ntp * 16) * RSTRIDE) + bOff);
            ldsm4(&blo[ntp * 4], cb + BLO + (u32)((n0w + ntp * 16) * RSTRIDE) + bOff);
        }
#pragma unroll
        for (int mt = 0; mt < 4; mt++) {
            u32 ahi[4], alo[4];
            ldsm4(ahi, cb + AHI + (u32)((m0w + mt * 16) * RSTRIDE) + aOff);
            ldsm4(alo, cb + ALO + (u32)((m0w + mt * 16) * RSTRIDE) + aOff);
#pragma unroll
            for (int nt = 0; nt < 4; nt++) {
                const u32* bh = &bhi[(nt >> 1) * 4 + (nt & 1) * 2];
                const u32* bl = &blo[(nt >> 1) * 4 + (nt & 1) * 2];
                mma_bf16(acc[mt][nt], ahi, bh[0], bh[1]);
                mma_bf16(acc[mt][nt], ahi, bl[0], bl[1]);
                mma_bf16(acc[mt][nt], alo, bh[0], bh[1]);
            }
        }
        __syncthreads();
    }

    // ---- epilogue ----
#pragma unroll
    for (int mt = 0; mt < 4; mt++) {
        int rA = r0 + m0w + mt * 16 + (lane >> 2);
        int rB = rA + 8;
        float mfA = 1.0f, mfB = 1.0f;
        if (use_mask) { mfA = g_maskf[rA]; mfB = g_maskf[rB]; }
#pragma unroll
        for (int nt = 0; nt < 4; nt++) {
            int n = n0g + n0w + nt * 8 + (lane & 3) * 2;
            float b0 = bias[n], b1 = bias[n + 1];
            float2 v0, v1;
            v0.x = (acc[mt][nt][0] + b0) * mfA;
            v0.y = (acc[mt][nt][1] + b1) * mfA;
            v1.x = (acc[mt][nt][2] + b0) * mfB;
            v1.y = (acc[mt][nt][3] + b1) * mfB;
            *(float2*)&Out[(size_t)rA * 256 + n] = v0;
            *(float2*)&Out[(size_t)rB * 256 + n] = v1;
        }
    }
}

// ---------------- kernel 3: pair-count inverse -------------------------------
__global__ void __launch_bounds__(256) cnt_kernel() {
    int b = blockIdx.x >> 8;
    int i = blockIdx.x & 255;
    int j = threadIdx.x;
    __shared__ float mi[MMT];
    if (j < MMT) mi[j] = g_maskf[(b * MMT + j) * NNT + i];
    __syncthreads();
    float s = 0.0f;
#pragma unroll 8
    for (int m = 0; m < MMT; m++)
        s = fmaf(mi[m], g_maskf[(b * MMT + m) * NNT + j], s);
    g_cinv[((size_t)b * NNT + i) * NNT + j] = 1.0f / ((float)MMT * (s + 1e-5f));
}

// ---------------- kernel 4: masked outer-mean contraction over m -------------
// outer[b][i][j][h] = cinv[b][i][j] * sum_m L[b,m,i,h] * R[b,m,j,h]
// fp32 SIMT (proven); epilogue writes bf16 hi/lo planes for the final GEMM.
__global__ void __launch_bounds__(256) outer_kernel() {
    __shared__ __align__(16) float Ls[8][8][68];  // [m][h][i] (+4 pad)
    __shared__ __align__(16) float Rs[8][8][32];  // [m][h][j]

    int tid = threadIdx.x;
    int hb = blockIdx.x;
    int jb = blockIdx.y;
    int zb = blockIdx.z;
    int b  = zb >> 2;
    int i0 = (zb & 3) * 64;
    int j0 = jb * 32;
    int h0 = hb * 8;

    int jg = tid & 7;
    int hg = (tid >> 3) & 3;
    int ig = tid >> 5;

    float acc[8][4][2];
#pragma unroll
    for (int ii = 0; ii < 8; ii++)
#pragma unroll
        for (int jj = 0; jj < 4; jj++) { acc[ii][jj][0] = 0.0f; acc[ii][jj][1] = 0.0f; }

    for (int mc = 0; mc < MMT; mc += 8) {
#pragma unroll
        for (int it = 0; it < 4; it++) {
            int f = it * 256 + tid;
            int hv = f & 1;
            int li = (f >> 1) & 63;
            int lm = f >> 7;
            float4 v = *(const float4*)
                &g_L[(((size_t)(b * MMT + mc + lm) * NNT + i0 + li) * HHT) + h0 + hv * 4];
            Ls[lm][hv * 4 + 0][li] = v.x;
            Ls[lm][hv * 4 + 1][li] = v.y;
            Ls[lm][hv * 4 + 2][li] = v.z;
            Ls[lm][hv * 4 + 3][li] = v.w;
        }
#pragma unroll
        for (int it = 0; it < 2; it++) {
            int f = it * 256 + tid;
            int hv = f & 1;
            int lj = (f >> 1) & 31;
            int lm = f >> 6;
            float4 v = *(const float4*)
                &g_R[(((size_t)(b * MMT + mc + lm) * NNT + j0 + lj) * HHT) + h0 + hv * 4];
            Rs[lm][hv * 4 + 0][lj] = v.x;
            Rs[lm][hv * 4 + 1][lj] = v.y;
            Rs[lm][hv * 4 + 2][lj] = v.z;
            Rs[lm][hv * 4 + 3][lj] = v.w;
        }
        __syncthreads();
#pragma unroll
        for (int lm = 0; lm < 8; lm++) {
            float4 l00 = *(const float4*)&Ls[lm][hg * 2 + 0][ig * 8];
            float4 l01 = *(const float4*)&Ls[lm][hg * 2 + 0][ig * 8 + 4];
            float4 l10 = *(const float4*)&Ls[lm][hg * 2 + 1][ig * 8];
            float4 l11 = *(const float4*)&Ls[lm][hg * 2 + 1][ig * 8 + 4];
            float4 r0v = *(const float4*)&Rs[lm][hg * 2 + 0][jg * 4];
            float4 r1v = *(const float4*)&Rs[lm][hg * 2 + 1][jg * 4];
            float lv0[8] = {l00.x, l00.y, l00.z, l00.w, l01.x, l01.y, l01.z, l01.w};
            float lv1[8] = {l10.x, l10.y, l10.z, l10.w, l11.x, l11.y, l11.z, l11.w};
            float rv0[4] = {r0v.x, r0v.y, r0v.z, r0v.w};
            float rv1[4] = {r1v.x, r1v.y, r1v.z, r1v.w};
#pragma unroll
            for (int ii = 0; ii < 8; ii++)
#pragma unroll
                for (int jj = 0; jj < 4; jj++) {
                    acc[ii][jj][0] = fmaf(lv0[ii], rv0[jj], acc[ii][jj][0]);
                    acc[ii][jj][1] = fmaf(lv1[ii], rv1[jj], acc[ii][jj][1]);
                }
        }
        __syncthreads();
    }

#pragma unroll
    for (int ii = 0; ii < 8; ii++) {
        int gi = i0 + ig * 8 + ii;
#pragma unroll
        for (int jj = 0; jj < 4; jj++) {
            int gj = j0 + jg * 4 + jj;
            float ci = g_cinv[((size_t)b * NNT + gi) * NNT + gj];
            size_t base = (((size_t)b * NNT + gi) * NNT + gj) * HHT + h0 + hg * 2;
            float v0 = acc[ii][jj][0] * ci;
            float v1 = acc[ii][jj][1] * ci;
            *(u32*)&g_oh[base] = pack2h(v0, v1);
            float r0f = v0 - __bfloat162float(__float2bfloat16(v0));
            float r1f = v1 - __bfloat162float(__float2bfloat16(v1));
            *(u32*)&g_ol[base] = pack2h(r0f, r1f);
        }
    }
}

// ---------------- launch ------------------------------------------------------
extern "C" void kernel_launch(void* const* d_in, const int* in_sizes, int n_in,
                              void* d_out, int out_size) {
    // metadata order: x, mask, ln_w, ln_b, Wl, bl, Wr, br, Wo, bo
    const float* x    = (const float*)d_in[0];
    const void*  mask = d_in[1];
    const float* ln_w = (const float*)d_in[2];
    const float* ln_b = (const float*)d_in[3];
    const float* Wl   = (const float*)d_in[4];
    const float* bl   = (const float*)d_in[5];
    const float* Wr   = (const float*)d_in[6];
    const float* br   = (const float*)d_in[7];
    const float* Wo   = (const float*)d_in[8];
    const float* bo   = (const float*)d_in[9];
    float* out = (float*)d_out;

    detect_mask_kernel<<<1, 256>>>((const u32*)mask);
    expand_mask_kernel<<<ROWS / 256, 256>>>(mask);
    wsplit_kernel<<<768, 256>>>(Wl, Wr, Wo);
    ln_kernel<<<ROWS / 8, 256>>>(x, ln_w, ln_b);
    cnt_kernel<<<BB * NNT, 256>>>();
    // projections: L and R (blockIdx.z selects)
    mm_kernel<<<dim3(2, ROWS / 128, 2), 256>>>(0, bl, br, nullptr);
    outer_kernel<<<dim3(HHT / 8, NNT / 32, BB * (NNT / 64)), 256>>>();
    // final GEMM: pair rows x Wo + bo
    mm_kernel<<<dim3(2, (int)(PAIRROWS / 128), 1), 256>>>(1, bo, nullptr, out);
}

// round 10
// speedup vs baseline: 2.2193x; 1.3258x over previous
#include <cuda_runtime.h>
#include <cuda_bf16.h>
#include <cstdint>
#include <cstddef>

// Problem constants (fixed by the reference setup)
#define BB   2
#define MMT  64
#define NNT  256
#define DDT  256
#define HHT  256
#define ROWS (BB*MMT*NNT)                 // 32768 token rows (b,m,i)
#define PAIRROWS ((size_t)BB*NNT*NNT)     // 131072 pair rows (b,i,j)

typedef unsigned int u32;
typedef unsigned long long u64;
typedef __nv_bfloat16 bf16;

// ---------------- scratch (device globals; no allocations allowed) ----------
__device__ __align__(16) bf16  g_xh[(size_t)ROWS * DDT];        // 16.8 MB
__device__ __align__(16) bf16  g_xl[(size_t)ROWS * DDT];        // 16.8 MB
// L/R as bf16 pair-words (lo16=hi part, hi16=lo part), layout [b][h][m][i]
__device__ __align__(16) u32   g_LP[(size_t)BB * HHT * MMT * NNT];  // 33.5 MB
__device__ __align__(16) u32   g_RP[(size_t)BB * HHT * MMT * NNT];  // 33.5 MB
// outer result planes, layout [b][h][i][j]
__device__ __align__(16) bf16  g_oh[(size_t)BB * HHT * NNT * NNT];  // 67 MB
__device__ __align__(16) bf16  g_ol[(size_t)BB * HHT * NNT * NNT];  // 67 MB
__device__ __align__(16) bf16  g_Wh[3][DDT * HHT];              // W^T hi [w][n*256+k]
__device__ __align__(16) bf16  g_Wlo[3][DDT * HHT];             // W^T lo
__device__ float g_maskf[ROWS];
__device__ float g_cinv[BB * NNT * NNT];
__device__ int   g_mask_mode;

// ---------------- helpers -----------------------------------------------------
__device__ __forceinline__ u32 smem_u32(const void* p) {
    u32 a;
    asm("{ .reg .u64 t; cvta.to.shared.u64 t, %1; cvt.u32.u64 %0, t; }"
        : "=r"(a) : "l"(p));
    return a;
}

#define CP16(dst, src) \
    asm volatile("cp.async.ca.shared.global [%0], [%1], 16;" :: "r"(dst), "l"(src))
#define CPCOMMIT() asm volatile("cp.async.commit_group;" ::: "memory")
#define CPWAIT(n)  asm volatile("cp.async.wait_group %0;" :: "n"(n) : "memory")

__device__ __forceinline__ void ldsm4(u32 r[4], u32 addr) {
    asm volatile("ldmatrix.sync.aligned.m8n8.x4.shared.b16 {%0,%1,%2,%3}, [%4];"
                 : "=r"(r[0]), "=r"(r[1]), "=r"(r[2]), "=r"(r[3]) : "r"(addr));
}
__device__ __forceinline__ void ldsm4t(u32 r[4], u32 addr) {
    asm volatile("ldmatrix.sync.aligned.m8n8.x4.trans.shared.b16 {%0,%1,%2,%3}, [%4];"
                 : "=r"(r[0]), "=r"(r[1]), "=r"(r[2]), "=r"(r[3]) : "r"(addr));
}

__device__ __forceinline__ void mma_bf16(float d[4], const u32 a[4], const u32 b0,
                                         const u32 b1) {
    asm volatile(
        "mma.sync.aligned.m16n8k16.row.col.f32.bf16.bf16.f32 "
        "{%0,%1,%2,%3}, {%4,%5,%6,%7}, {%8,%9}, {%0,%1,%2,%3};"
        : "+f"(d[0]), "+f"(d[1]), "+f"(d[2]), "+f"(d[3])
        : "r"(a[0]), "r"(a[1]), "r"(a[2]), "r"(a[3]), "r"(b0), "r"(b1));
}

// pair-word: lo16 = bf16(v), hi16 = bf16(v - hi)
__device__ __forceinline__ u32 pack_pw(float v) {
    bf16 h = __float2bfloat16(v);
    float r = v - __bfloat162float(h);
    return (u32)__bfloat16_as_ushort(h) |
           ((u32)__bfloat16_as_ushort(__float2bfloat16(r)) << 16);
}
// two hi-bf16 packed
__device__ __forceinline__ u32 pack2h(float a, float b) {
    return (u32)__bfloat16_as_ushort(__float2bfloat16(a)) |
           ((u32)__bfloat16_as_ushort(__float2bfloat16(b)) << 16);
}

// ---------------- kernel 0a: detect mask dtype -------------------------------
__global__ void detect_mask_kernel(const u32* p) {
    __shared__ int s_nonbin, s_nonfp;
    if (threadIdx.x == 0) { s_nonbin = 0; s_nonfp = 0; }
    __syncthreads();
    int nonbin = 0, nonfp = 0;
    for (int idx = threadIdx.x; idx < 8192; idx += 256) {
        u32 v = p[idx];
        if (v != 0u && v != 1u)           nonbin = 1;
        if (v != 0u && v != 0x3F800000u)  nonfp  = 1;
    }
    if (nonbin) atomicOr(&s_nonbin, 1);
    if (nonfp)  atomicOr(&s_nonfp, 1);
    __syncthreads();
    if (threadIdx.x == 0) {
        int mode;
        if      (!s_nonbin) mode = 0;
        else if (!s_nonfp)  mode = 1;
        else                mode = 2;
        g_mask_mode = mode;
    }
}

// ---------------- kernel 0b: expand mask to float ----------------------------
__global__ void expand_mask_kernel(const void* p) {
    int r = blockIdx.x * 256 + threadIdx.x;
    int mode = g_mask_mode;
    float f;
    if (mode == 0)      f = (((const int*)p)[r]           != 0)    ? 1.0f : 0.0f;
    else if (mode == 1) f = (((const float*)p)[r]         != 0.0f) ? 1.0f : 0.0f;
    else                f = (((const unsigned char*)p)[r] != 0)    ? 1.0f : 0.0f;
    g_maskf[r] = f;
}

// ---------------- kernel 0c: transpose + split weights -----------------------
__global__ void wsplit_kernel(const float* __restrict__ Wl,
                              const float* __restrict__ Wr,
                              const float* __restrict__ Wo) {
    int idx = blockIdx.x * 256 + threadIdx.x;
    int w = idx >> 16;
    int r = idx & 65535;
    int n = r >> 8, k = r & 255;
    const float* W = (w == 0) ? Wl : ((w == 1) ? Wr : Wo);
    float v = W[k * 256 + n];
    bf16 h = __float2bfloat16(v);
    g_Wh[w][n * 256 + k]  = h;
    g_Wlo[w][n * 256 + k] = __float2bfloat16(v - __bfloat162float(h));
}

// ---------------- kernel 1: LayerNorm (warp per row) -> bf16 planes ----------
__global__ void __launch_bounds__(256) ln_kernel(const float* __restrict__ x,
                                                 const float* __restrict__ w,
                                                 const float* __restrict__ bvec) {
    int lane = threadIdx.x & 31;
    int warp = threadIdx.x >> 5;
    int row  = blockIdx.x * 8 + warp;

    const float4* xr = (const float4*)&x[(size_t)row * DDT];
    float4 v0 = xr[lane * 2];
    float4 v1 = xr[lane * 2 + 1];

    float s  = v0.x + v0.y + v0.z + v0.w + v1.x + v1.y + v1.z + v1.w;
    float sq = v0.x * v0.x + v0.y * v0.y + v0.z * v0.z + v0.w * v0.w +
               v1.x * v1.x + v1.y * v1.y + v1.z * v1.z + v1.w * v1.w;
#pragma unroll
    for (int o = 16; o > 0; o >>= 1) {
        s  += __shfl_xor_sync(0xFFFFFFFFu, s,  o);
        sq += __shfl_xor_sync(0xFFFFFFFFu, sq, o);
    }
    float mu   = s * (1.0f / DDT);
    float var  = sq * (1.0f / DDT) - mu * mu;
    float rstd = rsqrtf(var + 1e-5f);

    const float4* wr = (const float4*)w;
    const float4* br = (const float4*)bvec;
    float4 w0 = wr[lane * 2], w1 = wr[lane * 2 + 1];
    float4 b0 = br[lane * 2], b1 = br[lane * 2 + 1];

    float y[8];
    y[0] = (v0.x - mu) * rstd * w0.x + b0.x;
    y[1] = (v0.y - mu) * rstd * w0.y + b0.y;
    y[2] = (v0.z - mu) * rstd * w0.z + b0.z;
    y[3] = (v0.w - mu) * rstd * w0.w + b0.w;
    y[4] = (v1.x - mu) * rstd * w1.x + b1.x;
    y[5] = (v1.y - mu) * rstd * w1.y + b1.y;
    y[6] = (v1.z - mu) * rstd * w1.z + b1.z;
    y[7] = (v1.w - mu) * rstd * w1.w + b1.w;

    uint4 hv, lv;
    hv.x = pack2h(y[0], y[1]);
    lv.x = pack2h(y[0] - __bfloat162float(__float2bfloat16(y[0])),
                  y[1] - __bfloat162float(__float2bfloat16(y[1])));
    hv.y = pack2h(y[2], y[3]);
    lv.y = pack2h(y[2] - __bfloat162float(__float2bfloat16(y[2])),
                  y[3] - __bfloat162float(__float2bfloat16(y[3])));
    hv.z = pack2h(y[4], y[5]);
    lv.z = pack2h(y[4] - __bfloat162float(__float2bfloat16(y[4])),
                  y[5] - __bfloat162float(__float2bfloat16(y[5])));
    hv.w = pack2h(y[6], y[7]);
    lv.w = pack2h(y[6] - __bfloat162float(__float2bfloat16(y[6])),
                  y[7] - __bfloat162float(__float2bfloat16(y[7])));

    *(uint4*)&g_xh[(size_t)row * DDT + lane * 8] = hv;
    *(uint4*)&g_xl[(size_t)row * DDT + lane * 8] = lv;
}

// ---------------- kernel 2: projection GEMM (transposed pair-word output) ----
// CTA 128(M rows = fixed b,m; i-range) x 128(N=h), K=256 in 16 chunks.
// Epilogue: (acc+bias)*mask -> pair-words at [b][h][m][i].
#define RSTRIDE 48
#define PLANE   (128 * RSTRIDE)           // 6144
#define BUFSZ   (4 * PLANE)               // 24576
#define AHI 0
#define ALO PLANE
#define BHI (2 * PLANE)
#define BLO (3 * PLANE)

__global__ void __launch_bounds__(256) proj_mm(const float* __restrict__ bias_l,
                                               const float* __restrict__ bias_r) {
    __shared__ __align__(16) char sm[2 * BUFSZ];   // 48 KB

    const int tid  = threadIdx.x;
    const int lane = tid & 31;
    const int wid  = tid >> 5;
    const int r0   = blockIdx.y * 128;
    const int n0g  = blockIdx.x * 128;
    const int m0w  = (wid >> 2) * 64;
    const int n0w  = (wid & 3) * 32;

    const bf16* Bh; const bf16* Bl; const float* bias; u32* OutP;
    if (blockIdx.z == 0) { Bh = g_Wh[0]; Bl = g_Wlo[0]; bias = bias_l; OutP = g_LP; }
    else                 { Bh = g_Wh[1]; Bl = g_Wlo[1]; bias = bias_r; OutP = g_RP; }

    const u32 smem = smem_u32(sm);
    const int srow = tid >> 1;
    const int sseg = tid & 1;
    const u32 sdst = (u32)(srow * RSTRIDE + sseg * 16);
    const size_t arow = (size_t)(r0 + srow) * 256 + sseg * 8;
    const size_t brow = (size_t)(n0g + srow) * 256 + sseg * 8;

    const u32 aOff = (u32)((lane & 15) * RSTRIDE + (lane >> 4) * 16);
    const u32 bOff = (u32)(((lane & 7) + ((lane >> 4) & 1) * 8) * RSTRIDE +
                           ((lane >> 3) & 1) * 16);

    float acc[4][4][4];
#pragma unroll
    for (int mt = 0; mt < 4; mt++)
#pragma unroll
        for (int nt = 0; nt < 4; nt++)
#pragma unroll
            for (int q = 0; q < 4; q++) acc[mt][nt][q] = 0.0f;

    {
        u32 base = smem;
        CP16(base + AHI + sdst, g_xh + arow);
        CP16(base + ALO + sdst, g_xl + arow);
        CP16(base + BHI + sdst, Bh + brow);
        CP16(base + BLO + sdst, Bl + brow);
        CPCOMMIT();
    }

    for (int c = 0; c < 16; c++) {
        if (c + 1 < 16) {
            u32 base = smem + (u32)(((c + 1) & 1) * BUFSZ);
            size_t koff = (size_t)(c + 1) * 16;
            CP16(base + AHI + sdst, g_xh + arow + koff);
            CP16(base + ALO + sdst, g_xl + arow + koff);
            CP16(base + BHI + sdst, Bh + brow + koff);
            CP16(base + BLO + sdst, Bl + brow + koff);
            CPCOMMIT();
            CPWAIT(1);
        } else {
            CPWAIT(0);
        }
        __syncthreads();

        const u32 cb = smem + (u32)((c & 1) * BUFSZ);
        u32 bhi[8], blo[8];
#pragma unroll
        for (int ntp = 0; ntp < 2; ntp++) {
            ldsm4(&bhi[ntp * 4], cb + BHI + (u32)((n0w + ntp * 16) * RSTRIDE) + bOff);
            ldsm4(&blo[ntp * 4], cb + BLO + (u32)((n0w + ntp * 16) * RSTRIDE) + bOff);
        }
#pragma unroll
        for (int mt = 0; mt < 4; mt++) {
            u32 ahi[4], alo[4];
            ldsm4(ahi, cb + AHI + (u32)((m0w + mt * 16) * RSTRIDE) + aOff);
            ldsm4(alo, cb + ALO + (u32)((m0w + mt * 16) * RSTRIDE) + aOff);
#pragma unroll
            for (int nt = 0; nt < 4; nt++) {
                const u32* bh = &bhi[(nt >> 1) * 4 + (nt & 1) * 2];
                const u32* bl = &blo[(nt >> 1) * 4 + (nt & 1) * 2];
                mma_bf16(acc[mt][nt], ahi, bh[0], bh[1]);
                mma_bf16(acc[mt][nt], ahi, bl[0], bl[1]);
                mma_bf16(acc[mt][nt], alo, bh[0], bh[1]);
            }
        }
        __syncthreads();
    }

    // ---- transposed epilogue: stage 64h x 128i pair-words, write [b][h][m][i]
    const int bB = r0 >> 14;            // b
    const int mB = (r0 >> 8) & 63;      // m
    const int i0 = r0 & 255;            // i tile origin
    u32* T = (u32*)sm;                  // [64][132] words (33792 B)
    const int half_mine = n0w >> 6;

    for (int half = 0; half < 2; half++) {
        __syncthreads();
        if (half_mine == half) {
#pragma unroll
            for (int mt = 0; mt < 4; mt++) {
                int iA = m0w + mt * 16 + (lane >> 2);
                int iB = iA + 8;
                float mfA = g_maskf[r0 + iA];
                float mfB = g_maskf[r0 + iB];
#pragma unroll
                for (int nt = 0; nt < 4; nt++) {
                    int nloc = n0w + nt * 8 + (lane & 3) * 2;
                    int hh = nloc - half * 64;
                    float b0 = bias[n0g + nloc], b1 = bias[n0g + nloc + 1];
                    T[hh * 132 + iA]       = pack_pw((acc[mt][nt][0] + b0) * mfA);
                    T[(hh + 1) * 132 + iA] = pack_pw((acc[mt][nt][1] + b1) * mfA);
                    T[hh * 132 + iB]       = pack_pw((acc[mt][nt][2] + b0) * mfB);
                    T[(hh + 1) * 132 + iB] = pack_pw((acc[mt][nt][3] + b1) * mfB);
                }
            }
        }
        __syncthreads();
        // cooperative coalesced write: warp wq handles h rows wq*8..wq*8+7
        int wq = tid >> 5;
#pragma unroll
        for (int rr = 0; rr < 8; rr++) {
            int hh = wq * 8 + rr;
            uint4 v = *(uint4*)&T[hh * 132 + lane * 4];
            int h = n0g + half * 64 + hh;
            *(uint4*)&OutP[(((size_t)(bB * 256 + h)) * 64 + mB) * 256 + i0 + lane * 4] = v;
        }
    }
}

// ---------------- kernel 3: pair-count inverse -------------------------------
__global__ void __launch_bounds__(256) cnt_kernel() {
    int b = blockIdx.x >> 8;
    int i = blockIdx.x & 255;
    int j = threadIdx.x;
    __shared__ float mi[MMT];
    if (j < MMT) mi[j] = g_maskf[(b * MMT + j) * NNT + i];
    __syncthreads();
    float s = 0.0f;
#pragma unroll 8
    for (int m = 0; m < MMT; m++)
        s = fmaf(mi[m], g_maskf[(b * MMT + m) * NNT + j], s);
    g_cinv[((size_t)b * NNT + i) * NNT + j] = 1.0f / ((float)MMT * (s + 1e-5f));
}

// ---------------- kernel 4: outer contraction as batched mma GEMM ------------
// Per (b,h): C[i][j] = sum_m L[h][m][i] * R[h][m][j]; A,B k-major stored ->
// ldmatrix.trans. CTA 128i x 128j, K=64 in 2 chunks of 32. Epilogue *cinv,
// writes bf16 hi/lo planes at [b][h][i][j].
#define OST  272                           // 128*2B + 16 pad
#define OPL  (32 * OST)                    // 8704 per plane-chunk
#define OAH  0
#define OAL  OPL
#define OBH  (2 * OPL)
#define OBL  (3 * OPL)

__global__ void __launch_bounds__(256) outer_mm() {
    __shared__ __align__(16) char sm[4 * OPL];   // 34816 B

    const int tid  = threadIdx.x;
    const int lane = tid & 31;
    const int wid  = tid >> 5;
    const int h  = blockIdx.x;
    const int i0 = (blockIdx.y >> 1) * 128;
    const int j0 = (blockIdx.y & 1) * 128;
    const int b  = blockIdx.z;
    const int m0w = (wid >> 2) * 64;   // i offset in tile
    const int n0w = (wid & 3) * 32;    // j offset in tile

    const u32* gL = g_LP + ((size_t)(b * 256 + h) * 64) * 256 + i0;
    const u32* gR = g_RP + ((size_t)(b * 256 + h) * 64) * 256 + j0;
    const u32 smem = smem_u32(sm);

    float acc[4][4][4];
#pragma unroll
    for (int mt = 0; mt < 4; mt++)
#pragma unroll
        for (int nt = 0; nt < 4; nt++)
#pragma unroll
            for (int q = 0; q < 4; q++) acc[mt][nt][q] = 0.0f;

    // trans ldmatrix lane-address offsets
    const u32 aOffT = (u32)(((lane & 7) + ((lane >> 4) & 1) * 8) * OST +
                            ((lane >> 3) & 1) * 16);
    const u32 bOffT = (u32)(((lane & 7) + ((lane >> 3) & 1) * 8) * OST +
                            ((lane >> 4) & 1) * 16);

    for (int mc = 0; mc < 64; mc += 32) {
        // stage 32m x 128 cols, byte_perm split into hi/lo planes
#pragma unroll
        for (int q = 0; q < 8; q++) {
            int idx = q * 256 + tid;          // 0..2047 uint2 slots
            int m  = idx >> 6;
            int ip = idx & 63;
            uint2 wa = *(const uint2*)&gL[(size_t)(mc + m) * 256 + ip * 2];
            *(u32*)(sm + OAH + m * OST + ip * 4) = __byte_perm(wa.x, wa.y, 0x5410);
            *(u32*)(sm + OAL + m * OST + ip * 4) = __byte_perm(wa.x, wa.y, 0x7632);
            uint2 wb = *(const uint2*)&gR[(size_t)(mc + m) * 256 + ip * 2];
            *(u32*)(sm + OBH + m * OST + ip * 4) = __byte_perm(wb.x, wb.y, 0x5410);
            *(u32*)(sm + OBL + m * OST + ip * 4) = __byte_perm(wb.x, wb.y, 0x7632);
        }
        __syncthreads();

#pragma unroll
        for (int s = 0; s < 2; s++) {
            const u32 krow = (u32)(s * 16 * OST);
            u32 bhi[8], blo[8];
#pragma unroll
            for (int ntp = 0; ntp < 2; ntp++) {
                u32 col = (u32)((n0w + ntp * 16) * 2);
                ldsm4t(&bhi[ntp * 4], smem + OBH + krow + col + bOffT);
                ldsm4t(&blo[ntp * 4], smem + OBL + krow + col + bOffT);
            }
#pragma unroll
            for (int mt = 0; mt < 4; mt++) {
                u32 ahi[4], alo[4];
                u32 col = (u32)((m0w + mt * 16) * 2);
                ldsm4t(ahi, smem + OAH + krow + col + aOffT);
                ldsm4t(alo, smem + OAL + krow + col + aOffT);
#pragma unroll
                for (int nt = 0; nt < 4; nt++) {
                    const u32* bh = &bhi[(nt >> 1) * 4 + (nt & 1) * 2];
                    const u32* bl = &blo[(nt >> 1) * 4 + (nt & 1) * 2];
                    mma_bf16(acc[mt][nt], ahi, bh[0], bh[1]);
                    mma_bf16(acc[mt][nt], ahi, bl[0], bl[1]);
                    mma_bf16(acc[mt][nt], alo, bh[0], bh[1]);
                }
            }
        }
        __syncthreads();
    }

    // epilogue: *cinv, write hi/lo planes [b][h][i][j]
    bf16* ohB = g_oh + (size_t)(b * 256 + h) * 65536;
    bf16* olB = g_ol + (size_t)(b * 256 + h) * 65536;
#pragma unroll
    for (int mt = 0; mt < 4; mt++) {
        int iA = i0 + m0w + mt * 16 + (lane >> 2);
        int iB = iA + 8;
#pragma unroll
        for (int nt = 0; nt < 4; nt++) {
            int gj = j0 + n0w + nt * 8 + (lane & 3) * 2;
            float c0A = g_cinv[((size_t)b * 256 + iA) * 256 + gj];
            float c1A = g_cinv[((size_t)b * 256 + iA) * 256 + gj + 1];
            float c0B = g_cinv[((size_t)b * 256 + iB) * 256 + gj];
            float c1B = g_cinv[((size_t)b * 256 + iB) * 256 + gj + 1];
            float s0 = acc[mt][nt][0] * c0A, s1 = acc[mt][nt][1] * c1A;
            float s2 = acc[mt][nt][2] * c0B, s3 = acc[mt][nt][3] * c1B;
            *(u32*)&ohB[(size_t)iA * 256 + gj] = pack2h(s0, s1);
            *(u32*)&olB[(size_t)iA * 256 + gj] = pack2h(
                s0 - __bfloat162float(__float2bfloat16(s0)),
                s1 - __bfloat162float(__float2bfloat16(s1)));
            *(u32*)&ohB[(size_t)iB * 256 + gj] = pack2h(s2, s3);
            *(u32*)&olB[(size_t)iB * 256 + gj] = pack2h(
                s2 - __bfloat162float(__float2bfloat16(s2)),
                s3 - __bfloat162float(__float2bfloat16(s3)));
        }
    }
}

// ---------------- kernel 5: final GEMM (A k-major via trans ldmatrix) --------
// out[r][d] = sum_h S[b][h][rloc] * Wo^T[d][h] + bo
#define FAST 272
#define FAPL (16 * FAST)          // 4352
#define FBST 48
#define FBPL (128 * FBST)         // 6144
#define FAH2 0
#define FAL2 FAPL
#define FBH2 (2 * FAPL)
#define FBL2 (2 * FAPL + FBPL)
#define FBUF (2 * FAPL + 2 * FBPL)   // 20992

__global__ void __launch_bounds__(256) final_mm(const float* __restrict__ bo,
                                                float* __restrict__ out) {
    __shared__ __align__(16) char sm[2 * FBUF];  // 41984 B

    const int tid  = threadIdx.x;
    const int lane = tid & 31;
    const int wid  = tid >> 5;
    const int r0   = blockIdx.y * 128;
    const int n0g  = blockIdx.x * 128;
    const int m0w  = (wid >> 2) * 64;
    const int n0w  = (wid & 3) * 32;
    const int b    = r0 >> 16;
    const int rl0  = r0 & 65535;

    const bf16* gAh = g_oh + (size_t)b * 256 * 65536 + rl0;
    const bf16* gAl = g_ol + (size_t)b * 256 * 65536 + rl0;
    const bf16* gBh = g_Wh[2];
    const bf16* gBl = g_Wlo[2];

    const u32 smem = smem_u32(sm);
    // A staging: 16h x 128r; thread: hh=tid>>4, piece=tid&15
    const int ahh = tid >> 4, apc = tid & 15;
    const u32 adst = (u32)(ahh * FAST + apc * 16);
    // B staging: 128n x 16k; thread: row=tid>>1, seg=tid&1
    const int srow = tid >> 1, sseg = tid & 1;
    const u32 bdst = (u32)(srow * FBST + sseg * 16);
    const size_t brow = (size_t)(n0g + srow) * 256 + sseg * 8;

    const u32 aOffT = (u32)(((lane & 7) + ((lane >> 4) & 1) * 8) * FAST +
                            ((lane >> 3) & 1) * 16);
    const u32 bOff  = (u32)(((lane & 7) + ((lane >> 4) & 1) * 8) * FBST +
                            ((lane >> 3) & 1) * 16);

    float acc[4][4][4];
#pragma unroll
    for (int mt = 0; mt < 4; mt++)
#pragma unroll
        for (int nt = 0; nt < 4; nt++)
#pragma unroll
            for (int q = 0; q < 4; q++) acc[mt][nt][q] = 0.0f;

    {
        u32 base = smem;
        CP16(base + FAH2 + adst, gAh + (size_t)ahh * 65536 + apc * 8);
        CP16(base + FAL2 + adst, gAl + (size_t)ahh * 65536 + apc * 8);
        CP16(base + FBH2 + bdst, gBh + brow);
        CP16(base + FBL2 + bdst, gBl + brow);
        CPCOMMIT();
    }

    for (int c = 0; c < 16; c++) {
        if (c + 1 < 16) {
            u32 base = smem + (u32)(((c + 1) & 1) * FBUF);
            size_t hoff = (size_t)(c + 1) * 16;
            CP16(base + FAH2 + adst, gAh + (hoff + ahh) * 65536 + apc * 8);
            CP16(base + FAL2 + adst, gAl + (hoff + ahh) * 65536 + apc * 8);
            CP16(base + FBH2 + bdst, gBh + brow + hoff);
            CP16(base + FBL2 + bdst, gBl + brow + hoff);
            CPCOMMIT();
            CPWAIT(1);
        } else {
            CPWAIT(0);
        }
        __syncthreads();

        const u32 cb = smem + (u32)((c & 1) * FBUF);
        u32 bhi[8], blo[8];
#pragma unroll
        for (int ntp = 0; ntp < 2; ntp++) {
            ldsm4(&bhi[ntp * 4], cb + FBH2 + (u32)((n0w + ntp * 16) * FBST) + bOff);
            ldsm4(&blo[ntp * 4], cb + FBL2 + (u32)((n0w + ntp * 16) * FBST) + bOff);
        }
#pragma unroll
        for (int mt = 0; mt < 4; mt++) {
            u32 ahi[4], alo[4];
            u32 col = (u32)((m0w + mt * 16) * 2);
            ldsm4t(ahi, cb + FAH2 + col + aOffT);
            ldsm4t(alo, cb + FAL2 + col + aOffT);
#pragma unroll
            for (int nt = 0; nt < 4; nt++) {
                const u32* bh = &bhi[(nt >> 1) * 4 + (nt & 1) * 2];
                const u32* bl = &blo[(nt >> 1) * 4 + (nt & 1) * 2];
                mma_bf16(acc[mt][nt], ahi, bh[0], bh[1]);
                mma_bf16(acc[mt][nt], ahi, bl[0], bl[1]);
                mma_bf16(acc[mt][nt], alo, bh[0], bh[1]);
            }
        }
        __syncthreads();
    }

#pragma unroll
    for (int mt = 0; mt < 4; mt++) {
        size_t rA = (size_t)(r0 + m0w + mt * 16 + (lane >> 2));
        size_t rB = rA + 8;
#pragma unroll
        for (int nt = 0; nt < 4; nt++) {
            int n = n0g + n0w + nt * 8 + (lane & 3) * 2;
            float b0 = bo[n], b1 = bo[n + 1];
            float2 v0, v1;
            v0.x = acc[mt][nt][0] + b0;
            v0.y = acc[mt][nt][1] + b1;
            v1.x = acc[mt][nt][2] + b0;
            v1.y = acc[mt][nt][3] + b1;
            *(float2*)&out[rA * 256 + n] = v0;
            *(float2*)&out[rB * 256 + n] = v1;
        }
    }
}

// ---------------- launch ------------------------------------------------------
extern "C" void kernel_launch(void* const* d_in, const int* in_sizes, int n_in,
                              void* d_out, int out_size) {
    // metadata order: x, mask, ln_w, ln_b, Wl, bl, Wr, br, Wo, bo
    const float* x    = (const float*)d_in[0];
    const void*  mask = d_in[1];
    const float* ln_w = (const float*)d_in[2];
    const float* ln_b = (const float*)d_in[3];
    const float* Wl   = (const float*)d_in[4];
    const float* bl   = (const float*)d_in[5];
    const float* Wr   = (const float*)d_in[6];
    const float* br   = (const float*)d_in[7];
    const float* Wo   = (const float*)d_in[8];
    const float* bo   = (const float*)d_in[9];
    float* out = (float*)d_out;

    detect_mask_kernel<<<1, 256>>>((const u32*)mask);
    expand_mask_kernel<<<ROWS / 256, 256>>>(mask);
    wsplit_kernel<<<768, 256>>>(Wl, Wr, Wo);
    ln_kernel<<<ROWS / 8, 256>>>(x, ln_w, ln_b);
    cnt_kernel<<<BB * NNT, 256>>>();
    proj_mm<<<dim3(2, 256, 2), 256>>>(bl, br);
    outer_mm<<<dim3(256, 4, 2), 256>>>();
    final_mm<<<dim3(2, 1024), 256>>>(bo, out);
}

// round 11
// speedup vs baseline: 3.0868x; 1.3909x over previous
#include <cuda_runtime.h>
#include <cuda_fp16.h>
#include <cstdint>
#include <cstddef>

// Problem constants (fixed by the reference setup)
#define BB   2
#define MMT  64
#define NNT  256
#define DDT  256
#define HHT  256
#define ROWS (BB*MMT*NNT)                 // 32768 token rows (b,m,i)

typedef unsigned int u32;
typedef unsigned long long u64;
typedef __half f16;

// ---------------- scratch (device globals; no allocations allowed) ----------
__device__ __align__(16) f16   g_xh[(size_t)ROWS * DDT];        // 16.8 MB  LN hi
__device__ __align__(16) f16   g_xl[(size_t)ROWS * DDT];        // 16.8 MB  LN lo
// L/R as fp16 pair-words (lo16=hi part, hi16=lo part), layout [b][h][m][i]
__device__ __align__(16) u32   g_LP[(size_t)BB * HHT * MMT * NNT];  // 33.5 MB
__device__ __align__(16) u32   g_RP[(size_t)BB * HHT * MMT * NNT];  // 33.5 MB
// outer result (single fp16), layout [b][h][i][j]
__device__ __align__(16) f16   g_oh[(size_t)BB * HHT * NNT * NNT];  // 67 MB
__device__ __align__(16) f16   g_Wh[3][DDT * HHT];              // W^T hi [w][n*256+k]
__device__ __align__(16) f16   g_Wlo[2][DDT * HHT];             // W^T lo (Wl, Wr only)
__device__ float g_maskf[ROWS];
__device__ float g_cinv[BB * NNT * NNT];
__device__ int   g_mask_mode;

// ---------------- helpers -----------------------------------------------------
__device__ __forceinline__ u32 smem_u32(const void* p) {
    u32 a;
    asm("{ .reg .u64 t; cvta.to.shared.u64 t, %1; cvt.u32.u64 %0, t; }"
        : "=r"(a) : "l"(p));
    return a;
}

#define CP16(dst, src) \
    asm volatile("cp.async.ca.shared.global [%0], [%1], 16;" :: "r"(dst), "l"(src))
#define CPCOMMIT() asm volatile("cp.async.commit_group;" ::: "memory")
#define CPWAIT(n)  asm volatile("cp.async.wait_group %0;" :: "n"(n) : "memory")

__device__ __forceinline__ void ldsm4(u32 r[4], u32 addr) {
    asm volatile("ldmatrix.sync.aligned.m8n8.x4.shared.b16 {%0,%1,%2,%3}, [%4];"
                 : "=r"(r[0]), "=r"(r[1]), "=r"(r[2]), "=r"(r[3]) : "r"(addr));
}
__device__ __forceinline__ void ldsm4t(u32 r[4], u32 addr) {
    asm volatile("ldmatrix.sync.aligned.m8n8.x4.trans.shared.b16 {%0,%1,%2,%3}, [%4];"
                 : "=r"(r[0]), "=r"(r[1]), "=r"(r[2]), "=r"(r[3]) : "r"(addr));
}

__device__ __forceinline__ void mma_f16(float d[4], const u32 a[4], const u32 b0,
                                        const u32 b1) {
    asm volatile(
        "mma.sync.aligned.m16n8k16.row.col.f32.f16.f16.f32 "
        "{%0,%1,%2,%3}, {%4,%5,%6,%7}, {%8,%9}, {%0,%1,%2,%3};"
        : "+f"(d[0]), "+f"(d[1]), "+f"(d[2]), "+f"(d[3])
        : "r"(a[0]), "r"(a[1]), "r"(a[2]), "r"(a[3]), "r"(b0), "r"(b1));
}

// pair-word: lo16 = f16(v), hi16 = f16(v - hi)
__device__ __forceinline__ u32 pack_pw(float v) {
    f16 h = __float2half_rn(v);
    float r = v - __half2float(h);
    return (u32)__half_as_ushort(h) |
           ((u32)__half_as_ushort(__float2half_rn(r)) << 16);
}
// two fp16 packed
__device__ __forceinline__ u32 pack2h(float a, float b) {
    return (u32)__half_as_ushort(__float2half_rn(a)) |
           ((u32)__half_as_ushort(__float2half_rn(b)) << 16);
}

// ---------------- kernel 0a: detect mask dtype -------------------------------
__global__ void detect_mask_kernel(const u32* p) {
    __shared__ int s_nonbin, s_nonfp;
    if (threadIdx.x == 0) { s_nonbin = 0; s_nonfp = 0; }
    __syncthreads();
    int nonbin = 0, nonfp = 0;
    for (int idx = threadIdx.x; idx < 8192; idx += 256) {
        u32 v = p[idx];
        if (v != 0u && v != 1u)           nonbin = 1;
        if (v != 0u && v != 0x3F800000u)  nonfp  = 1;
    }
    if (nonbin) atomicOr(&s_nonbin, 1);
    if (nonfp)  atomicOr(&s_nonfp, 1);
    __syncthreads();
    if (threadIdx.x == 0) {
        int mode;
        if      (!s_nonbin) mode = 0;
        else if (!s_nonfp)  mode = 1;
        else                mode = 2;
        g_mask_mode = mode;
    }
}

// ---------------- kernel 0b: expand mask to float ----------------------------
__global__ void expand_mask_kernel(const void* p) {
    int r = blockIdx.x * 256 + threadIdx.x;
    int mode = g_mask_mode;
    float f;
    if (mode == 0)      f = (((const int*)p)[r]           != 0)    ? 1.0f : 0.0f;
    else if (mode == 1) f = (((const float*)p)[r]         != 0.0f) ? 1.0f : 0.0f;
    else                f = (((const unsigned char*)p)[r] != 0)    ? 1.0f : 0.0f;
    g_maskf[r] = f;
}

// ---------------- kernel 0c: transpose + split weights -----------------------
__global__ void wsplit_kernel(const float* __restrict__ Wl,
                              const float* __restrict__ Wr,
                              const float* __restrict__ Wo) {
    int idx = blockIdx.x * 256 + threadIdx.x;
    int w = idx >> 16;
    int r = idx & 65535;
    int n = r >> 8, k = r & 255;
    const float* W = (w == 0) ? Wl : ((w == 1) ? Wr : Wo);
    float v = W[k * 256 + n];
    f16 h = __float2half_rn(v);
    g_Wh[w][n * 256 + k] = h;
    if (w < 2)
        g_Wlo[w][n * 256 + k] = __float2half_rn(v - __half2float(h));
}

// ---------------- kernel 1: LayerNorm (warp per row) -> fp16 planes ----------
__global__ void __launch_bounds__(256) ln_kernel(const float* __restrict__ x,
                                                 const float* __restrict__ w,
                                                 const float* __restrict__ bvec) {
    int lane = threadIdx.x & 31;
    int warp = threadIdx.x >> 5;
    int row  = blockIdx.x * 8 + warp;

    const float4* xr = (const float4*)&x[(size_t)row * DDT];
    float4 v0 = xr[lane * 2];
    float4 v1 = xr[lane * 2 + 1];

    float s  = v0.x + v0.y + v0.z + v0.w + v1.x + v1.y + v1.z + v1.w;
    float sq = v0.x * v0.x + v0.y * v0.y + v0.z * v0.z + v0.w * v0.w +
               v1.x * v1.x + v1.y * v1.y + v1.z * v1.z + v1.w * v1.w;
#pragma unroll
    for (int o = 16; o > 0; o >>= 1) {
        s  += __shfl_xor_sync(0xFFFFFFFFu, s,  o);
        sq += __shfl_xor_sync(0xFFFFFFFFu, sq, o);
    }
    float mu   = s * (1.0f / DDT);
    float var  = sq * (1.0f / DDT) - mu * mu;
    float rstd = rsqrtf(var + 1e-5f);

    const float4* wr = (const float4*)w;
    const float4* br = (const float4*)bvec;
    float4 w0 = wr[lane * 2], w1 = wr[lane * 2 + 1];
    float4 b0 = br[lane * 2], b1 = br[lane * 2 + 1];

    float y[8];
    y[0] = (v0.x - mu) * rstd * w0.x + b0.x;
    y[1] = (v0.y - mu) * rstd * w0.y + b0.y;
    y[2] = (v0.z - mu) * rstd * w0.z + b0.z;
    y[3] = (v0.w - mu) * rstd * w0.w + b0.w;
    y[4] = (v1.x - mu) * rstd * w1.x + b1.x;
    y[5] = (v1.y - mu) * rstd * w1.y + b1.y;
    y[6] = (v1.z - mu) * rstd * w1.z + b1.z;
    y[7] = (v1.w - mu) * rstd * w1.w + b1.w;

    uint4 hv, lv;
    hv.x = pack2h(y[0], y[1]);
    lv.x = pack2h(y[0] - __half2float(__float2half_rn(y[0])),
                  y[1] - __half2float(__float2half_rn(y[1])));
    hv.y = pack2h(y[2], y[3]);
    lv.y = pack2h(y[2] - __half2float(__float2half_rn(y[2])),
                  y[3] - __half2float(__float2half_rn(y[3])));
    hv.z = pack2h(y[4], y[5]);
    lv.z = pack2h(y[4] - __half2float(__float2half_rn(y[4])),
                  y[5] - __half2float(__float2half_rn(y[5])));
    hv.w = pack2h(y[6], y[7]);
    lv.w = pack2h(y[6] - __half2float(__float2half_rn(y[6])),
                  y[7] - __half2float(__float2half_rn(y[7])));

    *(uint4*)&g_xh[(size_t)row * DDT + lane * 8] = hv;
    *(uint4*)&g_xl[(size_t)row * DDT + lane * 8] = lv;
}

// ---------------- kernel 2: projection GEMM (fp16 split, transposed output) --
#define RSTRIDE 48
#define PLANE   (128 * RSTRIDE)           // 6144
#define BUFSZ   (4 * PLANE)               // 24576
#define AHI 0
#define ALO PLANE
#define BHI (2 * PLANE)
#define BLO (3 * PLANE)

__global__ void __launch_bounds__(256) proj_mm(const float* __restrict__ bias_l,
                                               const float* __restrict__ bias_r) {
    __shared__ __align__(16) char sm[2 * BUFSZ];   // 48 KB

    const int tid  = threadIdx.x;
    const int lane = tid & 31;
    const int wid  = tid >> 5;
    const int r0   = blockIdx.y * 128;
    const int n0g  = blockIdx.x * 128;
    const int m0w  = (wid >> 2) * 64;
    const int n0w  = (wid & 3) * 32;

    const f16* Bh; const f16* Bl; const float* bias; u32* OutP;
    if (blockIdx.z == 0) { Bh = g_Wh[0]; Bl = g_Wlo[0]; bias = bias_l; OutP = g_LP; }
    else                 { Bh = g_Wh[1]; Bl = g_Wlo[1]; bias = bias_r; OutP = g_RP; }

    const u32 smem = smem_u32(sm);
    const int srow = tid >> 1;
    const int sseg = tid & 1;
    const u32 sdst = (u32)(srow * RSTRIDE + sseg * 16);
    const size_t arow = (size_t)(r0 + srow) * 256 + sseg * 8;
    const size_t brow = (size_t)(n0g + srow) * 256 + sseg * 8;

    const u32 aOff = (u32)((lane & 15) * RSTRIDE + (lane >> 4) * 16);
    const u32 bOff = (u32)(((lane & 7) + ((lane >> 4) & 1) * 8) * RSTRIDE +
                           ((lane >> 3) & 1) * 16);

    float acc[4][4][4];
#pragma unroll
    for (int mt = 0; mt < 4; mt++)
#pragma unroll
        for (int nt = 0; nt < 4; nt++)
#pragma unroll
            for (int q = 0; q < 4; q++) acc[mt][nt][q] = 0.0f;

    {
        u32 base = smem;
        CP16(base + AHI + sdst, g_xh + arow);
        CP16(base + ALO + sdst, g_xl + arow);
        CP16(base + BHI + sdst, Bh + brow);
        CP16(base + BLO + sdst, Bl + brow);
        CPCOMMIT();
    }

    for (int c = 0; c < 16; c++) {
        if (c + 1 < 16) {
            u32 base = smem + (u32)(((c + 1) & 1) * BUFSZ);
            size_t koff = (size_t)(c + 1) * 16;
            CP16(base + AHI + sdst, g_xh + arow + koff);
            CP16(base + ALO + sdst, g_xl + arow + koff);
            CP16(base + BHI + sdst, Bh + brow + koff);
            CP16(base + BLO + sdst, Bl + brow + koff);
            CPCOMMIT();
            CPWAIT(1);
        } else {
            CPWAIT(0);
        }
        __syncthreads();

        const u32 cb = smem + (u32)((c & 1) * BUFSZ);
        u32 bhi[8], blo[8];
#pragma unroll
        for (int ntp = 0; ntp < 2; ntp++) {
            ldsm4(&bhi[ntp * 4], cb + BHI + (u32)((n0w + ntp * 16) * RSTRIDE) + bOff);
            ldsm4(&blo[ntp * 4], cb + BLO + (u32)((n0w + ntp * 16) * RSTRIDE) + bOff);
        }
#pragma unroll
        for (int mt = 0; mt < 4; mt++) {
            u32 ahi[4], alo[4];
            ldsm4(ahi, cb + AHI + (u32)((m0w + mt * 16) * RSTRIDE) + aOff);
            ldsm4(alo, cb + ALO + (u32)((m0w + mt * 16) * RSTRIDE) + aOff);
#pragma unroll
            for (int nt = 0; nt < 4; nt++) {
                const u32* bh = &bhi[(nt >> 1) * 4 + (nt & 1) * 2];
                const u32* bl = &blo[(nt >> 1) * 4 + (nt & 1) * 2];
                mma_f16(acc[mt][nt], ahi, bh[0], bh[1]);
                mma_f16(acc[mt][nt], ahi, bl[0], bl[1]);
                mma_f16(acc[mt][nt], alo, bh[0], bh[1]);
            }
        }
        __syncthreads();
    }

    // ---- transposed epilogue: stage 64h x 128i pair-words, write [b][h][m][i]
    const int bB = r0 >> 14;
    const int mB = (r0 >> 8) & 63;
    const int i0 = r0 & 255;
    u32* T = (u32*)sm;
    const int half_mine = n0w >> 6;

    for (int half = 0; half < 2; half++) {
        __syncthreads();
        if (half_mine == half) {
#pragma unroll
            for (int mt = 0; mt < 4; mt++) {
                int iA = m0w + mt * 16 + (lane >> 2);
                int iB = iA + 8;
                float mfA = g_maskf[r0 + iA];
                float mfB = g_maskf[r0 + iB];
#pragma unroll
                for (int nt = 0; nt < 4; nt++) {
                    int nloc = n0w + nt * 8 + (lane & 3) * 2;
                    int hh = nloc - half * 64;
                    float b0 = bias[n0g + nloc], b1 = bias[n0g + nloc + 1];
                    T[hh * 132 + iA]       = pack_pw((acc[mt][nt][0] + b0) * mfA);
                    T[(hh + 1) * 132 + iA] = pack_pw((acc[mt][nt][1] + b1) * mfA);
                    T[hh * 132 + iB]       = pack_pw((acc[mt][nt][2] + b0) * mfB);
                    T[(hh + 1) * 132 + iB] = pack_pw((acc[mt][nt][3] + b1) * mfB);
                }
            }
        }
        __syncthreads();
        int wq = tid >> 5;
#pragma unroll
        for (int rr = 0; rr < 8; rr++) {
            int hh = wq * 8 + rr;
            uint4 v = *(uint4*)&T[hh * 132 + lane * 4];
            int h = n0g + half * 64 + hh;
            *(uint4*)&OutP[(((size_t)(bB * 256 + h)) * 64 + mB) * 256 + i0 + lane * 4] = v;
        }
    }
}

// ---------------- kernel 3: pair-count inverse -------------------------------
__global__ void __launch_bounds__(256) cnt_kernel() {
    int b = blockIdx.x >> 8;
    int i = blockIdx.x & 255;
    int j = threadIdx.x;
    __shared__ float mi[MMT];
    if (j < MMT) mi[j] = g_maskf[(b * MMT + j) * NNT + i];
    __syncthreads();
    float s = 0.0f;
#pragma unroll 8
    for (int m = 0; m < MMT; m++)
        s = fmaf(mi[m], g_maskf[(b * MMT + m) * NNT + j], s);
    g_cinv[((size_t)b * NNT + i) * NNT + j] = 1.0f / ((float)MMT * (s + 1e-5f));
}

// ---------------- kernel 4: outer contraction (fp16 split batched MMA) -------
// Per (b,h): C[i][j] = sum_m L[h][m][i] * R[h][m][j]. Epilogue *cinv ->
// single fp16 at [b][h][i][j].
#define OST  272
#define OPL  (32 * OST)                    // 8704
#define OAH  0
#define OAL  OPL
#define OBH  (2 * OPL)
#define OBL  (3 * OPL)

__global__ void __launch_bounds__(256) outer_mm() {
    __shared__ __align__(16) char sm[4 * OPL];   // 34816 B

    const int tid  = threadIdx.x;
    const int lane = tid & 31;
    const int wid  = tid >> 5;
    const int h  = blockIdx.x;
    const int i0 = (blockIdx.y >> 1) * 128;
    const int j0 = (blockIdx.y & 1) * 128;
    const int b  = blockIdx.z;
    const int m0w = (wid >> 2) * 64;
    const int n0w = (wid & 3) * 32;

    const u32* gL = g_LP + ((size_t)(b * 256 + h) * 64) * 256 + i0;
    const u32* gR = g_RP + ((size_t)(b * 256 + h) * 64) * 256 + j0;
    const u32 smem = smem_u32(sm);

    float acc[4][4][4];
#pragma unroll
    for (int mt = 0; mt < 4; mt++)
#pragma unroll
        for (int nt = 0; nt < 4; nt++)
#pragma unroll
            for (int q = 0; q < 4; q++) acc[mt][nt][q] = 0.0f;

    const u32 aOffT = (u32)(((lane & 7) + ((lane >> 4) & 1) * 8) * OST +
                            ((lane >> 3) & 1) * 16);
    const u32 bOffT = (u32)(((lane & 7) + ((lane >> 3) & 1) * 8) * OST +
                            ((lane >> 4) & 1) * 16);

    for (int mc = 0; mc < 64; mc += 32) {
#pragma unroll
        for (int q = 0; q < 8; q++) {
            int idx = q * 256 + tid;
            int m  = idx >> 6;
            int ip = idx & 63;
            uint2 wa = *(const uint2*)&gL[(size_t)(mc + m) * 256 + ip * 2];
            *(u32*)(sm + OAH + m * OST + ip * 4) = __byte_perm(wa.x, wa.y, 0x5410);
            *(u32*)(sm + OAL + m * OST + ip * 4) = __byte_perm(wa.x, wa.y, 0x7632);
            uint2 wb = *(const uint2*)&gR[(size_t)(mc + m) * 256 + ip * 2];
            *(u32*)(sm + OBH + m * OST + ip * 4) = __byte_perm(wb.x, wb.y, 0x5410);
            *(u32*)(sm + OBL + m * OST + ip * 4) = __byte_perm(wb.x, wb.y, 0x7632);
        }
        __syncthreads();

#pragma unroll
        for (int s = 0; s < 2; s++) {
            const u32 krow = (u32)(s * 16 * OST);
            u32 bhi[8], blo[8];
#pragma unroll
            for (int ntp = 0; ntp < 2; ntp++) {
                u32 col = (u32)((n0w + ntp * 16) * 2);
                ldsm4t(&bhi[ntp * 4], smem + OBH + krow + col + bOffT);
                ldsm4t(&blo[ntp * 4], smem + OBL + krow + col + bOffT);
            }
#pragma unroll
            for (int mt = 0; mt < 4; mt++) {
                u32 ahi[4], alo[4];
                u32 col = (u32)((m0w + mt * 16) * 2);
                ldsm4t(ahi, smem + OAH + krow + col + aOffT);
                ldsm4t(alo, smem + OAL + krow + col + aOffT);
#pragma unroll
                for (int nt = 0; nt < 4; nt++) {
                    const u32* bh = &bhi[(nt >> 1) * 4 + (nt & 1) * 2];
                    const u32* bl = &blo[(nt >> 1) * 4 + (nt & 1) * 2];
                    mma_f16(acc[mt][nt], ahi, bh[0], bh[1]);
                    mma_f16(acc[mt][nt], ahi, bl[0], bl[1]);
                    mma_f16(acc[mt][nt], alo, bh[0], bh[1]);
                }
            }
        }
        __syncthreads();
    }

    // epilogue: *cinv, write single fp16 plane [b][h][i][j]
    f16* ohB = g_oh + (size_t)(b * 256 + h) * 65536;
#pragma unroll
    for (int mt = 0; mt < 4; mt++) {
        int iA = i0 + m0w + mt * 16 + (lane >> 2);
        int iB = iA + 8;
#pragma unroll
        for (int nt = 0; nt < 4; nt++) {
            int gj = j0 + n0w + nt * 8 + (lane & 3) * 2;
            float c0A = g_cinv[((size_t)b * 256 + iA) * 256 + gj];
            float c1A = g_cinv[((size_t)b * 256 + iA) * 256 + gj + 1];
            float c0B = g_cinv[((size_t)b * 256 + iB) * 256 + gj];
            float c1B = g_cinv[((size_t)b * 256 + iB) * 256 + gj + 1];
            *(u32*)&ohB[(size_t)iA * 256 + gj] =
                pack2h(acc[mt][nt][0] * c0A, acc[mt][nt][1] * c1A);
            *(u32*)&ohB[(size_t)iB * 256 + gj] =
                pack2h(acc[mt][nt][2] * c0B, acc[mt][nt][3] * c1B);
        }
    }
}

// ---------------- kernel 5: final GEMM (single-pass fp16) --------------------
// out[r][d] = sum_h S[b][h][rloc] * Wo^T[d][h] + bo
#define FAST 272
#define FAPL (16 * FAST)          // 4352
#define FBST 48
#define FBPL (128 * FBST)         // 6144
#define FAH2 0
#define FBH2 FAPL
#define FBUF (FAPL + FBPL)        // 10496

__global__ void __launch_bounds__(256) final_mm(const float* __restrict__ bo,
                                                float* __restrict__ out) {
    __shared__ __align__(16) char sm[2 * FBUF];  // 20992 B

    const int tid  = threadIdx.x;
    const int lane = tid & 31;
    const int wid  = tid >> 5;
    const int r0   = blockIdx.y * 128;
    const int n0g  = blockIdx.x * 128;
    const int m0w  = (wid >> 2) * 64;
    const int n0w  = (wid & 3) * 32;
    const int b    = r0 >> 16;
    const int rl0  = r0 & 65535;

    const f16* gAh = g_oh + (size_t)b * 256 * 65536 + rl0;
    const f16* gBh = g_Wh[2];

    const u32 smem = smem_u32(sm);
    const int ahh = tid >> 4, apc = tid & 15;
    const u32 adst = (u32)(ahh * FAST + apc * 16);
    const int srow = tid >> 1, sseg = tid & 1;
    const u32 bdst = (u32)(srow * FBST + sseg * 16);
    const size_t brow = (size_t)(n0g + srow) * 256 + sseg * 8;

    const u32 aOffT = (u32)(((lane & 7) + ((lane >> 4) & 1) * 8) * FAST +
                            ((lane >> 3) & 1) * 16);
    const u32 bOff  = (u32)(((lane & 7) + ((lane >> 4) & 1) * 8) * FBST +
                            ((lane >> 3) & 1) * 16);

    float acc[4][4][4];
#pragma unroll
    for (int mt = 0; mt < 4; mt++)
#pragma unroll
        for (int nt = 0; nt < 4; nt++)
#pragma unroll
            for (int q = 0; q < 4; q++) acc[mt][nt][q] = 0.0f;

    {
        u32 base = smem;
        CP16(base + FAH2 + adst, gAh + (size_t)ahh * 65536 + apc * 8);
        CP16(base + FBH2 + bdst, gBh + brow);
        CPCOMMIT();
    }

    for (int c = 0; c < 16; c++) {
        if (c + 1 < 16) {
            u32 base = smem + (u32)(((c + 1) & 1) * FBUF);
            size_t hoff = (size_t)(c + 1) * 16;
            CP16(base + FAH2 + adst, gAh + (hoff + ahh) * 65536 + apc * 8);
            CP16(base + FBH2 + bdst, gBh + brow + hoff);
            CPCOMMIT();
            CPWAIT(1);
        } else {
            CPWAIT(0);
        }
        __syncthreads();

        const u32 cb = smem + (u32)((c & 1) * FBUF);
        u32 bhi[8];
#pragma unroll
        for (int ntp = 0; ntp < 2; ntp++)
            ldsm4(&bhi[ntp * 4], cb + FBH2 + (u32)((n0w + ntp * 16) * FBST) + bOff);
#pragma unroll
        for (int mt = 0; mt < 4; mt++) {
            u32 ahi[4];
            u32 col = (u32)((m0w + mt * 16) * 2);
            ldsm4t(ahi, cb + FAH2 + col + aOffT);
#pragma unroll
            for (int nt = 0; nt < 4; nt++) {
                const u32* bh = &bhi[(nt >> 1) * 4 + (nt & 1) * 2];
                mma_f16(acc[mt][nt], ahi, bh[0], bh[1]);
            }
        }
        __syncthreads();
    }

#pragma unroll
    for (int mt = 0; mt < 4; mt++) {
        size_t rA = (size_t)(r0 + m0w + mt * 16 + (lane >> 2));
        size_t rB = rA + 8;
#pragma unroll
        for (int nt = 0; nt < 4; nt++) {
            int n = n0g + n0w + nt * 8 + (lane & 3) * 2;
            float b0 = bo[n], b1 = bo[n + 1];
            float2 v0, v1;
            v0.x = acc[mt][nt][0] + b0;
            v0.y = acc[mt][nt][1] + b1;
            v1.x = acc[mt][nt][2] + b0;
            v1.y = acc[mt][nt][3] + b1;
            *(float2*)&out[rA * 256 + n] = v0;
            *(float2*)&out[rB * 256 + n] = v1;
        }
    }
}

// ---------------- launch ------------------------------------------------------
extern "C" void kernel_launch(void* const* d_in, const int* in_sizes, int n_in,
                              void* d_out, int out_size) {
    // metadata order: x, mask, ln_w, ln_b, Wl, bl, Wr, br, Wo, bo
    const float* x    = (const float*)d_in[0];
    const void*  mask = d_in[1];
    const float* ln_w = (const float*)d_in[2];
    const float* ln_b = (const float*)d_in[3];
    const float* Wl   = (const float*)d_in[4];
    const float* bl   = (const float*)d_in[5];
    const float* Wr   = (const float*)d_in[6];
    const float* br   = (const float*)d_in[7];
    const float* Wo   = (const float*)d_in[8];
    const float* bo   = (const float*)d_in[9];
    float* out = (float*)d_out;

    detect_mask_kernel<<<1, 256>>>((const u32*)mask);
    expand_mask_kernel<<<ROWS / 256, 256>>>(mask);
    wsplit_kernel<<<768, 256>>>(Wl, Wr, Wo);
    ln_kernel<<<ROWS / 8, 256>>>(x, ln_w, ln_b);
    cnt_kernel<<<BB * NNT, 256>>>();
    proj_mm<<<dim3(2, 256, 2), 256>>>(bl, br);
    outer_mm<<<dim3(256, 4, 2), 256>>>();
    final_mm<<<dim3(2, 1024), 256>>>(bo, out);
}

// round 12
// speedup vs baseline: 4.1925x; 1.3582x over previous
#include <cuda_runtime.h>
#include <cuda_fp16.h>
#include <cstdint>
#include <cstddef>

// Problem constants (fixed by the reference setup)
#define BB   2
#define MMT  64
#define NNT  256
#define DDT  256
#define HHT  256
#define ROWS (BB*MMT*NNT)                 // 32768 token rows (b,m,i)

typedef unsigned int u32;
typedef unsigned long long u64;
typedef __half f16;

// ---------------- scratch (device globals; no allocations allowed) ----------
__device__ __align__(16) f16   g_xh[(size_t)ROWS * DDT];            // 16.8 MB LN
__device__ __align__(16) f16   g_LP[(size_t)BB * HHT * MMT * NNT];  // 16.8 MB [b][h][m][i]
__device__ __align__(16) f16   g_RP[(size_t)BB * HHT * MMT * NNT];  // 16.8 MB
__device__ __align__(16) f16   g_oh[(size_t)BB * HHT * NNT * NNT];  // 67 MB [b][h][i][j]
__device__ __align__(16) f16   g_Wh[3][DDT * HHT];                  // W^T [w][n*256+k]
__device__ float g_maskf[ROWS];
__device__ float g_cinv[BB * NNT * NNT];
__device__ int   g_mask_mode;

// ---------------- helpers -----------------------------------------------------
__device__ __forceinline__ u32 smem_u32(const void* p) {
    u32 a;
    asm("{ .reg .u64 t; cvta.to.shared.u64 t, %1; cvt.u32.u64 %0, t; }"
        : "=r"(a) : "l"(p));
    return a;
}

#define CP16(dst, src) \
    asm volatile("cp.async.ca.shared.global [%0], [%1], 16;" :: "r"(dst), "l"(src))
#define CPCOMMIT() asm volatile("cp.async.commit_group;" ::: "memory")
#define CPWAIT(n)  asm volatile("cp.async.wait_group %0;" :: "n"(n) : "memory")

__device__ __forceinline__ void ldsm4(u32 r[4], u32 addr) {
    asm volatile("ldmatrix.sync.aligned.m8n8.x4.shared.b16 {%0,%1,%2,%3}, [%4];"
                 : "=r"(r[0]), "=r"(r[1]), "=r"(r[2]), "=r"(r[3]) : "r"(addr));
}
__device__ __forceinline__ void ldsm4t(u32 r[4], u32 addr) {
    asm volatile("ldmatrix.sync.aligned.m8n8.x4.trans.shared.b16 {%0,%1,%2,%3}, [%4];"
                 : "=r"(r[0]), "=r"(r[1]), "=r"(r[2]), "=r"(r[3]) : "r"(addr));
}

__device__ __forceinline__ void mma_f16(float d[4], const u32 a[4], const u32 b0,
                                        const u32 b1) {
    asm volatile(
        "mma.sync.aligned.m16n8k16.row.col.f32.f16.f16.f32 "
        "{%0,%1,%2,%3}, {%4,%5,%6,%7}, {%8,%9}, {%0,%1,%2,%3};"
        : "+f"(d[0]), "+f"(d[1]), "+f"(d[2]), "+f"(d[3])
        : "r"(a[0]), "r"(a[1]), "r"(a[2]), "r"(a[3]), "r"(b0), "r"(b1));
}

// two fp16 packed
__device__ __forceinline__ u32 pack2h(float a, float b) {
    return (u32)__half_as_ushort(__float2half_rn(a)) |
           ((u32)__half_as_ushort(__float2half_rn(b)) << 16);
}

// ---------------- kernel 0a: detect mask dtype -------------------------------
__global__ void detect_mask_kernel(const u32* p) {
    __shared__ int s_nonbin, s_nonfp;
    if (threadIdx.x == 0) { s_nonbin = 0; s_nonfp = 0; }
    __syncthreads();
    int nonbin = 0, nonfp = 0;
    for (int idx = threadIdx.x; idx < 8192; idx += 256) {
        u32 v = p[idx];
        if (v != 0u && v != 1u)           nonbin = 1;
        if (v != 0u && v != 0x3F800000u)  nonfp  = 1;
    }
    if (nonbin) atomicOr(&s_nonbin, 1);
    if (nonfp)  atomicOr(&s_nonfp, 1);
    __syncthreads();
    if (threadIdx.x == 0) {
        int mode;
        if      (!s_nonbin) mode = 0;
        else if (!s_nonfp)  mode = 1;
        else                mode = 2;
        g_mask_mode = mode;
    }
}

// ---------------- kernel 0b: expand mask to float ----------------------------
__global__ void expand_mask_kernel(const void* p) {
    int r = blockIdx.x * 256 + threadIdx.x;
    int mode = g_mask_mode;
    float f;
    if (mode == 0)      f = (((const int*)p)[r]           != 0)    ? 1.0f : 0.0f;
    else if (mode == 1) f = (((const float*)p)[r]         != 0.0f) ? 1.0f : 0.0f;
    else                f = (((const unsigned char*)p)[r] != 0)    ? 1.0f : 0.0f;
    g_maskf[r] = f;
}

// ---------------- kernel 0c: transpose weights to fp16 -----------------------
__global__ void wsplit_kernel(const float* __restrict__ Wl,
                              const float* __restrict__ Wr,
                              const float* __restrict__ Wo) {
    int idx = blockIdx.x * 256 + threadIdx.x;
    int w = idx >> 16;
    int r = idx & 65535;
    int n = r >> 8, k = r & 255;
    const float* W = (w == 0) ? Wl : ((w == 1) ? Wr : Wo);
    g_Wh[w][n * 256 + k] = __float2half_rn(W[k * 256 + n]);
}

// ---------------- kernel 1: LayerNorm (warp per row) -> fp16 ------------------
__global__ void __launch_bounds__(256) ln_kernel(const float* __restrict__ x,
                                                 const float* __restrict__ w,
                                                 const float* __restrict__ bvec) {
    int lane = threadIdx.x & 31;
    int warp = threadIdx.x >> 5;
    int row  = blockIdx.x * 8 + warp;

    const float4* xr = (const float4*)&x[(size_t)row * DDT];
    float4 v0 = xr[lane * 2];
    float4 v1 = xr[lane * 2 + 1];

    float s  = v0.x + v0.y + v0.z + v0.w + v1.x + v1.y + v1.z + v1.w;
    float sq = v0.x * v0.x + v0.y * v0.y + v0.z * v0.z + v0.w * v0.w +
               v1.x * v1.x + v1.y * v1.y + v1.z * v1.z + v1.w * v1.w;
#pragma unroll
    for (int o = 16; o > 0; o >>= 1) {
        s  += __shfl_xor_sync(0xFFFFFFFFu, s,  o);
        sq += __shfl_xor_sync(0xFFFFFFFFu, sq, o);
    }
    float mu   = s * (1.0f / DDT);
    float var  = sq * (1.0f / DDT) - mu * mu;
    float rstd = rsqrtf(var + 1e-5f);

    const float4* wr = (const float4*)w;
    const float4* br = (const float4*)bvec;
    float4 w0 = wr[lane * 2], w1 = wr[lane * 2 + 1];
    float4 b0 = br[lane * 2], b1 = br[lane * 2 + 1];

    uint4 hv;
    hv.x = pack2h((v0.x - mu) * rstd * w0.x + b0.x,
                  (v0.y - mu) * rstd * w0.y + b0.y);
    hv.y = pack2h((v0.z - mu) * rstd * w0.z + b0.z,
                  (v0.w - mu) * rstd * w0.w + b0.w);
    hv.z = pack2h((v1.x - mu) * rstd * w1.x + b1.x,
                  (v1.y - mu) * rstd * w1.y + b1.y);
    hv.w = pack2h((v1.z - mu) * rstd * w1.z + b1.z,
                  (v1.w - mu) * rstd * w1.w + b1.w);

    *(uint4*)&g_xh[(size_t)row * DDT + lane * 8] = hv;
}

// ---------------- kernel 2: projection GEMM (single fp16, transposed out) ----
#define RSTRIDE 48
#define PLANE   (128 * RSTRIDE)           // 6144
#define BUFSZ   (2 * PLANE)               // 12288: A at 0, B at PLANE
#define SM_PROJ (2 * BUFSZ)               // 24576 (epilogue reuses: 64*136*2=17408)

__global__ void __launch_bounds__(256) proj_mm(const float* __restrict__ bias_l,
                                               const float* __restrict__ bias_r) {
    __shared__ __align__(16) char sm[SM_PROJ];

    const int tid  = threadIdx.x;
    const int lane = tid & 31;
    const int wid  = tid >> 5;
    const int r0   = blockIdx.y * 128;
    const int n0g  = blockIdx.x * 128;
    const int m0w  = (wid >> 2) * 64;
    const int n0w  = (wid & 3) * 32;

    const f16* Bh; const float* bias; f16* OutP;
    if (blockIdx.z == 0) { Bh = g_Wh[0]; bias = bias_l; OutP = g_LP; }
    else                 { Bh = g_Wh[1]; bias = bias_r; OutP = g_RP; }

    const u32 smem = smem_u32(sm);
    const int srow = tid >> 1;
    const int sseg = tid & 1;
    const u32 sdst = (u32)(srow * RSTRIDE + sseg * 16);
    const size_t arow = (size_t)(r0 + srow) * 256 + sseg * 8;
    const size_t brow = (size_t)(n0g + srow) * 256 + sseg * 8;

    const u32 aOff = (u32)((lane & 15) * RSTRIDE + (lane >> 4) * 16);
    const u32 bOff = (u32)(((lane & 7) + ((lane >> 4) & 1) * 8) * RSTRIDE +
                           ((lane >> 3) & 1) * 16);

    float acc[4][4][4];
#pragma unroll
    for (int mt = 0; mt < 4; mt++)
#pragma unroll
        for (int nt = 0; nt < 4; nt++)
#pragma unroll
            for (int q = 0; q < 4; q++) acc[mt][nt][q] = 0.0f;

    {
        u32 base = smem;
        CP16(base + sdst, g_xh + arow);
        CP16(base + PLANE + sdst, Bh + brow);
        CPCOMMIT();
    }

    for (int c = 0; c < 16; c++) {
        if (c + 1 < 16) {
            u32 base = smem + (u32)(((c + 1) & 1) * BUFSZ);
            size_t koff = (size_t)(c + 1) * 16;
            CP16(base + sdst, g_xh + arow + koff);
            CP16(base + PLANE + sdst, Bh + brow + koff);
            CPCOMMIT();
            CPWAIT(1);
        } else {
            CPWAIT(0);
        }
        __syncthreads();

        const u32 cb = smem + (u32)((c & 1) * BUFSZ);
        u32 bhi[8];
#pragma unroll
        for (int ntp = 0; ntp < 2; ntp++)
            ldsm4(&bhi[ntp * 4], cb + PLANE + (u32)((n0w + ntp * 16) * RSTRIDE) + bOff);
#pragma unroll
        for (int mt = 0; mt < 4; mt++) {
            u32 ahi[4];
            ldsm4(ahi, cb + (u32)((m0w + mt * 16) * RSTRIDE) + aOff);
#pragma unroll
            for (int nt = 0; nt < 4; nt++) {
                const u32* bh = &bhi[(nt >> 1) * 4 + (nt & 1) * 2];
                mma_f16(acc[mt][nt], ahi, bh[0], bh[1]);
            }
        }
        __syncthreads();
    }

    // ---- transposed epilogue: stage 64h x 128i fp16, write [b][h][m][i] -----
    const int bB = r0 >> 14;
    const int mB = (r0 >> 8) & 63;
    const int i0 = r0 & 255;
    f16* T = (f16*)sm;                    // [64][136] halves, 272B row stride
    const int half_mine = n0w >> 6;

    for (int half = 0; half < 2; half++) {
        __syncthreads();
        if (half_mine == half) {
#pragma unroll
            for (int mt = 0; mt < 4; mt++) {
                int iA = m0w + mt * 16 + (lane >> 2);
                int iB = iA + 8;
                float mfA = g_maskf[r0 + iA];
                float mfB = g_maskf[r0 + iB];
#pragma unroll
                for (int nt = 0; nt < 4; nt++) {
                    int nloc = n0w + nt * 8 + (lane & 3) * 2;
                    int hh = nloc - half * 64;
                    float b0 = bias[n0g + nloc], b1 = bias[n0g + nloc + 1];
                    T[hh * 136 + iA]       = __float2half_rn((acc[mt][nt][0] + b0) * mfA);
                    T[(hh + 1) * 136 + iA] = __float2half_rn((acc[mt][nt][1] + b1) * mfA);
                    T[hh * 136 + iB]       = __float2half_rn((acc[mt][nt][2] + b0) * mfB);
                    T[(hh + 1) * 136 + iB] = __float2half_rn((acc[mt][nt][3] + b1) * mfB);
                }
            }
        }
        __syncthreads();
        int wq = tid >> 5;
#pragma unroll
        for (int rr = 0; rr < 8; rr++) {
            int hh = wq * 8 + rr;
            uint2 v = *(uint2*)&T[hh * 136 + lane * 4];
            int h = n0g + half * 64 + hh;
            *(uint2*)&OutP[(((size_t)(bB * 256 + h)) * 64 + mB) * 256 + i0 + lane * 4] = v;
        }
    }
}

// ---------------- kernel 3: pair-count inverse -------------------------------
__global__ void __launch_bounds__(256) cnt_kernel() {
    int b = blockIdx.x >> 8;
    int i = blockIdx.x & 255;
    int j = threadIdx.x;
    __shared__ float mi[MMT];
    if (j < MMT) mi[j] = g_maskf[(b * MMT + j) * NNT + i];
    __syncthreads();
    float s = 0.0f;
#pragma unroll 8
    for (int m = 0; m < MMT; m++)
        s = fmaf(mi[m], g_maskf[(b * MMT + m) * NNT + j], s);
    g_cinv[((size_t)b * NNT + i) * NNT + j] = 1.0f / ((float)MMT * (s + 1e-5f));
}

// ---------------- kernel 4: outer contraction (single fp16 batched MMA) ------
// Per (b,h): C[i][j] = sum_m L[h][m][i] * R[h][m][j]; full K=64 staged at once.
#define OST  272                           // 128*2B + 16 pad
#define OAB  0
#define OBB  (64 * OST)                    // 17408
#define SM_OUT (2 * 64 * OST)              // 34816

__global__ void __launch_bounds__(256) outer_mm() {
    __shared__ __align__(16) char sm[SM_OUT];

    const int tid  = threadIdx.x;
    const int lane = tid & 31;
    const int wid  = tid >> 5;
    const int h  = blockIdx.x;
    const int i0 = (blockIdx.y >> 1) * 128;
    const int j0 = (blockIdx.y & 1) * 128;
    const int b  = blockIdx.z;
    const int m0w = (wid >> 2) * 64;
    const int n0w = (wid & 3) * 32;

    const f16* gL = g_LP + ((size_t)(b * 256 + h) * 64) * 256 + i0;
    const f16* gR = g_RP + ((size_t)(b * 256 + h) * 64) * 256 + j0;
    const u32 smem = smem_u32(sm);

    float acc[4][4][4];
#pragma unroll
    for (int mt = 0; mt < 4; mt++)
#pragma unroll
        for (int nt = 0; nt < 4; nt++)
#pragma unroll
            for (int q = 0; q < 4; q++) acc[mt][nt][q] = 0.0f;

    const u32 aOffT = (u32)(((lane & 7) + ((lane >> 4) & 1) * 8) * OST +
                            ((lane >> 3) & 1) * 16);
    const u32 bOffT = (u32)(((lane & 7) + ((lane >> 3) & 1) * 8) * OST +
                            ((lane >> 4) & 1) * 16);

    // stage full 64m x 128col tiles for both A and B
#pragma unroll
    for (int q = 0; q < 8; q++) {
        int idx = q * 256 + tid;           // 0..2047
        int arr = idx >> 10;               // 0 = A(L), 1 = B(R)
        int rem = idx & 1023;
        int m   = rem >> 4;
        int pc  = rem & 15;
        const f16* src = (arr ? gR : gL) + (size_t)m * 256 + pc * 8;
        CP16(smem + (u32)(arr * OBB + m * OST + pc * 16), src);
    }
    CPCOMMIT();
    CPWAIT(0);
    __syncthreads();

#pragma unroll
    for (int s = 0; s < 4; s++) {
        const u32 krow = (u32)(s * 16 * OST);
        u32 bhi[8];
#pragma unroll
        for (int ntp = 0; ntp < 2; ntp++) {
            u32 col = (u32)((n0w + ntp * 16) * 2);
            ldsm4t(&bhi[ntp * 4], smem + OBB + krow + col + bOffT);
        }
#pragma unroll
        for (int mt = 0; mt < 4; mt++) {
            u32 ahi[4];
            u32 col = (u32)((m0w + mt * 16) * 2);
            ldsm4t(ahi, smem + OAB + krow + col + aOffT);
#pragma unroll
            for (int nt = 0; nt < 4; nt++) {
                const u32* bh = &bhi[(nt >> 1) * 4 + (nt & 1) * 2];
                mma_f16(acc[mt][nt], ahi, bh[0], bh[1]);
            }
        }
    }

    // epilogue: *cinv, write fp16 plane [b][h][i][j]
    f16* ohB = g_oh + (size_t)(b * 256 + h) * 65536;
#pragma unroll
    for (int mt = 0; mt < 4; mt++) {
        int iA = i0 + m0w + mt * 16 + (lane >> 2);
        int iB = iA + 8;
#pragma unroll
        for (int nt = 0; nt < 4; nt++) {
            int gj = j0 + n0w + nt * 8 + (lane & 3) * 2;
            float c0A = g_cinv[((size_t)b * 256 + iA) * 256 + gj];
            float c1A = g_cinv[((size_t)b * 256 + iA) * 256 + gj + 1];
            float c0B = g_cinv[((size_t)b * 256 + iB) * 256 + gj];
            float c1B = g_cinv[((size_t)b * 256 + iB) * 256 + gj + 1];
            *(u32*)&ohB[(size_t)iA * 256 + gj] =
                pack2h(acc[mt][nt][0] * c0A, acc[mt][nt][1] * c1A);
            *(u32*)&ohB[(size_t)iB * 256 + gj] =
                pack2h(acc[mt][nt][2] * c0B, acc[mt][nt][3] * c1B);
        }
    }
}

// ---------------- kernel 5: final GEMM (single-pass fp16) --------------------
// out[r][d] = sum_h S[b][h][rloc] * Wo^T[d][h] + bo
#define FAST 272
#define FAPL (16 * FAST)          // 4352
#define FBST 48
#define FBPL (128 * FBST)         // 6144
#define FAH2 0
#define FBH2 FAPL
#define FBUF (FAPL + FBPL)        // 10496

__global__ void __launch_bounds__(256) final_mm(const float* __restrict__ bo,
                                                float* __restrict__ out) {
    __shared__ __align__(16) char sm[2 * FBUF];  // 20992 B

    const int tid  = threadIdx.x;
    const int lane = tid & 31;
    const int wid  = tid >> 5;
    const int r0   = blockIdx.y * 128;
    const int n0g  = blockIdx.x * 128;
    const int m0w  = (wid >> 2) * 64;
    const int n0w  = (wid & 3) * 32;
    const int b    = r0 >> 16;
    const int rl0  = r0 & 65535;

    const f16* gAh = g_oh + (size_t)b * 256 * 65536 + rl0;
    const f16* gBh = g_Wh[2];

    const u32 smem = smem_u32(sm);
    const int ahh = tid >> 4, apc = tid & 15;
    const u32 adst = (u32)(ahh * FAST + apc * 16);
    const int srow = tid >> 1, sseg = tid & 1;
    const u32 bdst = (u32)(srow * FBST + sseg * 16);
    const size_t brow = (size_t)(n0g + srow) * 256 + sseg * 8;

    const u32 aOffT = (u32)(((lane & 7) + ((lane >> 4) & 1) * 8) * FAST +
                            ((lane >> 3) & 1) * 16);
    const u32 bOff  = (u32)(((lane & 7) + ((lane >> 4) & 1) * 8) * FBST +
                            ((lane >> 3) & 1) * 16);

    float acc[4][4][4];
#pragma unroll
    for (int mt = 0; mt < 4; mt++)
#pragma unroll
        for (int nt = 0; nt < 4; nt++)
#pragma unroll
            for (int q = 0; q < 4; q++) acc[mt][nt][q] = 0.0f;

    {
        u32 base = smem;
        CP16(base + FAH2 + adst, gAh + (size_t)ahh * 65536 + apc * 8);
        CP16(base + FBH2 + bdst, gBh + brow);
        CPCOMMIT();
    }

    for (int c = 0; c < 16; c++) {
        if (c + 1 < 16) {
            u32 base = smem + (u32)(((c + 1) & 1) * FBUF);
            size_t hoff = (size_t)(c + 1) * 16;
            CP16(base + FAH2 + adst, gAh + (hoff + ahh) * 65536 + apc * 8);
            CP16(base + FBH2 + bdst, gBh + brow + hoff);
            CPCOMMIT();
            CPWAIT(1);
        } else {
            CPWAIT(0);
        }
        __syncthreads();

        const u32 cb = smem + (u32)((c & 1) * FBUF);
        u32 bhi[8];
#pragma unroll
        for (int ntp = 0; ntp < 2; ntp++)
            ldsm4(&bhi[ntp * 4], cb + FBH2 + (u32)((n0w + ntp * 16) * FBST) + bOff);
#pragma unroll
        for (int mt = 0; mt < 4; mt++) {
            u32 ahi[4];
            u32 col = (u32)((m0w + mt * 16) * 2);
            ldsm4t(ahi, cb + FAH2 + col + aOffT);
#pragma unroll
            for (int nt = 0; nt < 4; nt++) {
                const u32* bh = &bhi[(nt >> 1) * 4 + (nt & 1) * 2];
                mma_f16(acc[mt][nt], ahi, bh[0], bh[1]);
            }
        }
        __syncthreads();
    }

#pragma unroll
    for (int mt = 0; mt < 4; mt++) {
        size_t rA = (size_t)(r0 + m0w + mt * 16 + (lane >> 2));
        size_t rB = rA + 8;
#pragma unroll
        for (int nt = 0; nt < 4; nt++) {
            int n = n0g + n0w + nt * 8 + (lane & 3) * 2;
            float b0 = bo[n], b1 = bo[n + 1];
            float2 v0, v1;
            v0.x = acc[mt][nt][0] + b0;
            v0.y = acc[mt][nt][1] + b1;
            v1.x = acc[mt][nt][2] + b0;
            v1.y = acc[mt][nt][3] + b1;
            *(float2*)&out[rA * 256 + n] = v0;
            *(float2*)&out[rB * 256 + n] = v1;
        }
    }
}

// ---------------- launch ------------------------------------------------------
extern "C" void kernel_launch(void* const* d_in, const int* in_sizes, int n_in,
                              void* d_out, int out_size) {
    // metadata order: x, mask, ln_w, ln_b, Wl, bl, Wr, br, Wo, bo
    const float* x    = (const float*)d_in[0];
    const void*  mask = d_in[1];
    const float* ln_w = (const float*)d_in[2];
    const float* ln_b = (const float*)d_in[3];
    const float* Wl   = (const float*)d_in[4];
    const float* bl   = (const float*)d_in[5];
    const float* Wr   = (const float*)d_in[6];
    const float* br   = (const float*)d_in[7];
    const float* Wo   = (const float*)d_in[8];
    const float* bo   = (const float*)d_in[9];
    float* out = (float*)d_out;

    detect_mask_kernel<<<1, 256>>>((const u32*)mask);
    expand_mask_kernel<<<ROWS / 256, 256>>>(mask);
    wsplit_kernel<<<768, 256>>>(Wl, Wr, Wo);
    ln_kernel<<<ROWS / 8, 256>>>(x, ln_w, ln_b);
    cnt_kernel<<<BB * NNT, 256>>>();
    proj_mm<<<dim3(2, 256, 2), 256>>>(bl, br);
    outer_mm<<<dim3(256, 4, 2), 256>>>();
    final_mm<<<dim3(2, 1024), 256>>>(bo, out);
}